// round 12
// baseline (speedup 1.0000x reference)
#include <cuda_runtime.h>
#include <cuda_fp16.h>
#include <math_constants.h>
#include <cstdint>

#define NN    8192
#define HID   128
#define OUTD  40
#define RSQRT_HD 0.17677669529663687f
#define L2E      1.4426950408889634f
#define MSH      (-4.0f * 1.4426950408889634f)

__device__ __align__(16) float  g_h   [NN * HID];
__device__ __align__(16) __half g_h16 [NN * HID];
__device__ __align__(16) __half g_qh  [NN * HID];
__device__ __align__(16) __half g_kh  [NN * HID];
__device__ __align__(16) __half g_vt  [HID * NN];
__device__ __align__(16) __half g_ao  [NN * HID];
__device__ __align__(16) float  g_h2  [NN * HID];
__device__ __align__(16) __half g_ipw16[3*HID*HID];
__device__ __align__(16) __half g_opw16[HID*HID];

__device__ __forceinline__ uint32_t smem_u32(const void* p){
    uint32_t a;
    asm("{ .reg .u64 t; cvta.to.shared.u64 t, %1; cvt.u32.u64 %0, t; }" : "=r"(a) : "l"(p));
    return a;
}
__device__ __forceinline__ void ldsm4(uint32_t r[4], uint32_t addr){
    asm volatile("ldmatrix.sync.aligned.m8n8.x4.shared.b16 {%0,%1,%2,%3}, [%4];"
        : "=r"(r[0]), "=r"(r[1]), "=r"(r[2]), "=r"(r[3]) : "r"(addr));
}
__device__ __forceinline__ void mmaf16(float c[4], const uint32_t a[4], const uint32_t b[2]){
    asm volatile("mma.sync.aligned.m16n8k16.row.col.f32.f16.f16.f32 "
        "{%0,%1,%2,%3}, {%4,%5,%6,%7}, {%8,%9}, {%0,%1,%2,%3};"
        : "+f"(c[0]), "+f"(c[1]), "+f"(c[2]), "+f"(c[3])
        : "r"(a[0]), "r"(a[1]), "r"(a[2]), "r"(a[3]), "r"(b[0]), "r"(b[1]));
}
__device__ __forceinline__ uint32_t packh2(float hi, float lo){
    uint32_t r; asm("cvt.rn.f16x2.f32 %0, %1, %2;" : "=r"(r) : "f"(hi), "f"(lo)); return r;
}
__device__ __forceinline__ uint32_t ex2h2(uint32_t a){
    uint32_t d; asm("ex2.approx.f16x2 %0, %1;" : "=r"(d) : "r"(a)); return d;
}
__device__ __forceinline__ uint32_t mulh2(uint32_t a, uint32_t b){
    uint32_t d; asm("mul.rn.f16x2 %0, %1, %2;" : "=r"(d) : "r"(a), "r"(b)); return d;
}
__device__ __forceinline__ float2 h2f2(uint32_t h){
    __half2 v = *(__half2*)&h; return __half22float2(v);
}
__device__ __forceinline__ uint32_t e16(float s, uint32_t lutaddr, float scale){
    int idx = __float2int_rn(s);
    uint32_t h;
    if (__int2float_rn(idx) == s && idx >= 0 && idx <= 10) {
        asm volatile("ld.shared.u16 %0, [%1];" : "=r"(h) : "r"(lutaddr + idx*2));
    } else {
        float ss = (isnan(s) || isinf(s)) ? -1.0f : s;
        float r = __fdividef(1.0f, ss);
        if (isnan(r) || isinf(r)) r = 0.0f;
        float e = exp2f(fmaf(scale, r, -scale) * L2E);
        h = (uint32_t)__half_as_ushort(__float2half_rn(e));
    }
    return h;
}

// ---------- weight convert ----------
__global__ __launch_bounds__(256)
void wcvt_k(const float* __restrict__ a, const float* __restrict__ b,
            __half* __restrict__ a16, __half* __restrict__ b16)
{
    int idx = blockIdx.x*256 + threadIdx.x;          // grid 64 -> 16384 threads
    for (int i = idx; i < 3*HID*HID; i += 16384) a16[i] = __float2half_rn(a[i]);
    for (int i = idx; i < HID*HID;   i += 16384) b16[i] = __float2half_rn(b[i]);
}

// ---------- fp32 GEMM (gemm1: mode3 fp32+f16 copy; Wout: mode0) ----------
#define GEMM_SMEM_BYTES ((2*128*64 + 64*132) * 4)

__global__ __launch_bounds__(256, 2)
void gemm_k(const float* __restrict__ A, const float* __restrict__ W,
            const float* __restrict__ bias, float* __restrict__ C,
            int CO, int mode, __half* __restrict__ c16)
{
    extern __shared__ float sm[];
    float* At  = sm;
    float* Wt  = sm + 128*64;
    float* Stg = sm + 2*128*64;
    const int r0  = blockIdx.x * 64;
    const int c0  = blockIdx.y * 64;
    const int tid = threadIdx.x;

    {
        const float4* Af4 = (const float4*)(A + (size_t)r0 * 128);
        float4* Sf4 = (float4*)Stg;
        #pragma unroll
        for (int i = 0; i < 8; i++) {
            int idx = tid + 256*i;
            int r = idx >> 5, d4 = idx & 31;
            Sf4[r*33 + d4] = Af4[r*32 + d4];
        }
    }
    __syncthreads();
    {
        #pragma unroll
        for (int i = 0; i < 8; i++) {
            int idx = tid + 256*i;
            int r = idx & 63, d4 = idx >> 6;
            float4 v = *(const float4*)&Stg[r*132 + d4*4];
            At[(4*d4+0)*64 + r] = v.x; At[(4*d4+1)*64 + r] = v.y;
            At[(4*d4+2)*64 + r] = v.z; At[(4*d4+3)*64 + r] = v.w;
        }
    }
    __syncthreads();
    {
        const float4* Wf4 = (const float4*)W;
        float4* Sf4 = (float4*)Stg;
        #pragma unroll
        for (int i = 0; i < 8; i++) {
            int idx = tid + 256*i;
            int c = idx >> 5, d4 = idx & 31;
            float4 v = make_float4(0.f,0.f,0.f,0.f);
            if (c0 + c < CO) v = Wf4[(size_t)(c0 + c)*32 + d4];
            Sf4[c*33 + d4] = v;
        }
    }
    __syncthreads();
    {
        #pragma unroll
        for (int i = 0; i < 8; i++) {
            int idx = tid + 256*i;
            int c = idx & 63, d4 = idx >> 6;
            float4 v = *(const float4*)&Stg[c*132 + d4*4];
            Wt[(4*d4+0)*64 + c] = v.x; Wt[(4*d4+1)*64 + c] = v.y;
            Wt[(4*d4+2)*64 + c] = v.z; Wt[(4*d4+3)*64 + c] = v.w;
        }
    }
    __syncthreads();

    const int tr = tid >> 4;
    const int tc = tid & 15;
    float acc[4][4];
    #pragma unroll
    for (int i = 0; i < 4; i++)
        #pragma unroll
        for (int j = 0; j < 4; j++) acc[i][j] = 0.f;

    #pragma unroll 8
    for (int d = 0; d < 128; d++) {
        float4 a = *(const float4*)&At[d*64 + tr*4];
        float4 w = *(const float4*)&Wt[d*64 + tc*4];
        float av[4] = {a.x, a.y, a.z, a.w};
        float wv[4] = {w.x, w.y, w.z, w.w};
        #pragma unroll
        for (int i = 0; i < 4; i++)
            #pragma unroll
            for (int j = 0; j < 4; j++)
                acc[i][j] = fmaf(av[i], wv[j], acc[i][j]);
    }

    #pragma unroll
    for (int i = 0; i < 4; i++) {
        int r = r0 + tr*4 + i;
        #pragma unroll
        for (int j = 0; j < 4; j++) {
            int c = c0 + tc*4 + j;
            if (c < CO) {
                float v = acc[i][j] + bias[c];
                C[(size_t)r*CO + c] = v;
                if (mode == 3) c16[(size_t)r*128 + c] = __float2half_rn(v);
            }
        }
    }
}

// ---------- f16 tensor-core GEMM: C[M,CO] = A[M,128] @ W[CO,128]^T + b ----------
// CTA 128 rows x 64 cols, 8 warps (4 row-groups x 2 col-groups), K=128 single stage.
// mode 2: qkv epilogue -> qh (scaled), kh, vt ; mode 1: h2 = R + relu(v) fp32
#define G16_AS   0
#define G16_WS   34816
#define G16_SMEM 52224

__global__ __launch_bounds__(256, 2)
void gemm16_k(const __half* __restrict__ A, const __half* __restrict__ W,
              const float* __restrict__ bias, const float* __restrict__ R,
              float* __restrict__ C, int mode,
              __half* __restrict__ qh, __half* __restrict__ kh, __half* __restrict__ vt)
{
    extern __shared__ char smc[];
    const uint32_t sb = smem_u32(smc);
    const int tid  = threadIdx.x;
    const int lane = tid & 31;
    const int wid  = tid >> 5;
    const int r0   = blockIdx.x * 128;
    const int c0   = blockIdx.y * 64;

    {   // load A tile: 128 rows x 16 uint4
        const uint4* Asrc = (const uint4*)A;
        #pragma unroll
        for (int i = 0; i < 8; i++) {
            int idx = tid + 256*i;
            int r = idx >> 4, c = idx & 15;
            *(uint4*)(smc + G16_AS + r*272 + c*16) = Asrc[(size_t)(r0 + r)*16 + c];
        }
        const uint4* Wsrc = (const uint4*)W;
        #pragma unroll
        for (int i = 0; i < 4; i++) {
            int idx = tid + 256*i;
            int r = idx >> 4, c = idx & 15;
            *(uint4*)(smc + G16_WS + r*272 + c*16) = Wsrc[(size_t)(c0 + r)*16 + c];
        }
    }
    __syncthreads();

    const int mrow = (wid >> 1) * 32;
    const int ncol = (wid & 1) * 32;
    const uint32_t aaddr = sb + G16_AS + (mrow + (lane & 15))*272 + ((lane >> 4) & 1)*16;
    const uint32_t baddr = sb + G16_WS + (ncol + (lane & 7) + ((lane >> 4) & 1)*8)*272
                           + ((lane >> 3) & 1)*16;

    float acc[2][4][4];
    #pragma unroll
    for (int mt = 0; mt < 2; mt++)
        #pragma unroll
        for (int nt = 0; nt < 4; nt++)
            #pragma unroll
            for (int e = 0; e < 4; e++) acc[mt][nt][e] = 0.f;

    #pragma unroll
    for (int k = 0; k < 8; k++) {
        uint32_t af[2][4], bf[2][4];
        ldsm4(af[0], aaddr + k*32);
        ldsm4(af[1], aaddr + 16*272 + k*32);
        ldsm4(bf[0], baddr + k*32);
        ldsm4(bf[1], baddr + 16*272 + k*32);
        #pragma unroll
        for (int mt = 0; mt < 2; mt++)
            #pragma unroll
            for (int p = 0; p < 2; p++) {
                mmaf16(acc[mt][2*p],   af[mt], bf[p]);
                mmaf16(acc[mt][2*p+1], af[mt], bf[p] + 2);
            }
    }

    const int rb = r0 + mrow + (lane >> 2);
    const int cb = c0 + ncol + 2*(lane & 3);
    #pragma unroll
    for (int mt = 0; mt < 2; mt++) {
        #pragma unroll
        for (int nt = 0; nt < 4; nt++) {
            int r = rb + mt*16;
            int c = cb + nt*8;
            float v0 = acc[mt][nt][0] + bias[c];
            float v1 = acc[mt][nt][1] + bias[c+1];
            float v2 = acc[mt][nt][2] + bias[c];
            float v3 = acc[mt][nt][3] + bias[c+1];
            if (mode == 2) {
                if (c < 128) {
                    *(__half2*)(qh + (size_t)r*128 + c)     = __floats2half2_rn(v0*RSQRT_HD, v1*RSQRT_HD);
                    *(__half2*)(qh + (size_t)(r+8)*128 + c) = __floats2half2_rn(v2*RSQRT_HD, v3*RSQRT_HD);
                } else if (c < 256) {
                    *(__half2*)(kh + (size_t)r*128 + (c-128))     = __floats2half2_rn(v0, v1);
                    *(__half2*)(kh + (size_t)(r+8)*128 + (c-128)) = __floats2half2_rn(v2, v3);
                } else {
                    vt[(size_t)(c-256)*NN + r]       = __float2half_rn(v0);
                    vt[(size_t)(c-255)*NN + r]       = __float2half_rn(v1);
                    vt[(size_t)(c-256)*NN + (r+8)]   = __float2half_rn(v2);
                    vt[(size_t)(c-255)*NN + (r+8)]   = __float2half_rn(v3);
                }
            } else {
                float2 R0 = *(const float2*)(R + (size_t)r*128 + c);
                float2 R1 = *(const float2*)(R + (size_t)(r+8)*128 + c);
                *(float2*)(C + (size_t)r*128 + c)     = make_float2(R0.x + fmaxf(v0,0.f), R0.y + fmaxf(v1,0.f));
                *(float2*)(C + (size_t)(r+8)*128 + c) = make_float2(R1.x + fmaxf(v2,0.f), R1.y + fmaxf(v3,0.f));
            }
        }
    }
}

// ---------- flash attention (R11 structure; fp32 l accumulation, f16 out) ----------
#define STAGE     45056
#define LUT_OFF   90112
#define ATTN_SMEM 90240

__global__ __launch_bounds__(256, 1)
void attn_k(const __half* __restrict__ qh_g, const __half* __restrict__ kh_g,
            const __half* __restrict__ vt_g, const float* __restrict__ sp,
            const float* __restrict__ scale_ptr, __half* __restrict__ out)
{
    extern __shared__ char smc[];
    const uint32_t sb = smem_u32(smc);
    const int tid  = threadIdx.x;
    const int lane = tid & 31;
    const int wid  = tid >> 5;
    const int h    = wid >> 1;
    const int qhf  = wid & 1;
    const int q0   = blockIdx.x * 64;
    const float scale = scale_ptr[0];
    const uint32_t lut = sb + LUT_OFF;

    if (tid <= 10) {
        float e = (tid == 0) ? expf(-scale) : expf(scale / (float)tid - scale);
        uint32_t hb = (uint32_t)__half_as_ushort(__float2half_rn(e));
        asm volatile("st.shared.u16 [%0], %1;" :: "r"(lut + tid*2), "r"(hb));
    }
    {
        const uint4* qsrc = (const uint4*)(qh_g + (size_t)q0 * 128);
        #pragma unroll
        for (int i = 0; i < 4; i++) {
            int idx = tid + 256*i;
            int r = idx >> 4, c = idx & 15;
            *(uint4*)(smc + STAGE + r*272 + c*16) = qsrc[r*16 + c];
        }
    }
    __syncthreads();
    uint32_t qa[2][2][4];
    #pragma unroll
    for (int mt = 0; mt < 2; mt++) {
        uint32_t qaddr = sb + STAGE + (qhf*32 + mt*16 + (lane & 15))*272
                         + (h*4 + (lane >> 4))*16;
        ldsm4(qa[mt][0], qaddr);
        ldsm4(qa[mt][1], qaddr + 32);
    }

    const uint32_t kaddr0 = sb + ((lane & 7) + ((lane >> 4) & 1)*8)*272
                            + h*64 + ((lane >> 3) & 1)*16;
    const uint32_t vaddr0 = sb + 17408 + (h*32 + (lane & 7) + ((lane >> 4) & 1)*8)*144
                            + ((lane >> 3) & 1)*16;
    const uint32_t baddr0 = sb + 35840 + (qhf*32 + (lane >> 2))*144 + (lane & 3)*32;

    float O[2][4][4];
    #pragma unroll
    for (int mt = 0; mt < 2; mt++)
        #pragma unroll
        for (int i = 0; i < 4; i++)
            #pragma unroll
            for (int j = 0; j < 4; j++) O[mt][i][j] = 0.f;
    float lsum[2][2] = {{0.f,0.f},{0.f,0.f}};

    const uint4* ksrc = (const uint4*)kh_g;
    const uint4* vsrc = (const uint4*)vt_g;

    const int kr = tid >> 4, kc = tid & 15;
    const int vr = tid >> 3, vc = tid & 7;
    const int bj  = kc >> 1;
    const int bc0 = (2*kc) & 3, bc1 = (2*kc + 1) & 3;

    uint4  krg[4], vrg[4];
    float4 brg[4];
    #pragma unroll
    for (int i = 0; i < 4; i++) {
        krg[i] = ksrc[(size_t)(kr + 16*i)*16 + kc];
        vrg[i] = vsrc[(size_t)(vr + 32*i)*1024 + vc];
        brg[i] = *(const float4*)(sp + (size_t)(q0 + kr + 16*i)*NN + kc*4);
    }
    {
        #pragma unroll
        for (int i = 0; i < 4; i++) {
            *(uint4*)(smc + (kr + 16*i)*272 + kc*16) = krg[i];
            *(uint4*)(smc + 17408 + (vr + 32*i)*144 + vc*16) = vrg[i];
            float4 s4 = brg[i];
            uint32_t p0 = (e16(s4.y, lut, scale) << 16) | e16(s4.x, lut, scale);
            uint32_t p1 = (e16(s4.w, lut, scale) << 16) | e16(s4.z, lut, scale);
            uint32_t bb = 35840 + (kr + 16*i)*144 + bj*4;
            *(uint32_t*)(smc + bb + bc0*32) = p0;
            *(uint32_t*)(smc + bb + bc1*32) = p1;
        }
        #pragma unroll
        for (int i = 0; i < 4; i++) {
            krg[i] = ksrc[(size_t)(64 + kr + 16*i)*16 + kc];
            vrg[i] = vsrc[(size_t)(vr + 32*i)*1024 + 8 + vc];
            brg[i] = *(const float4*)(sp + (size_t)(q0 + kr + 16*i)*NN + 64 + kc*4);
        }
    }

    for (int kb = 0; kb < NN/64; kb++) {
        __syncthreads();
        const uint32_t cur = (kb & 1) * STAGE;
        const uint32_t nxt = ((kb + 1) & 1) * STAGE;

        if (kb < NN/64 - 1) {
            #pragma unroll
            for (int i = 0; i < 4; i++) {
                *(uint4*)(smc + nxt + (kr + 16*i)*272 + kc*16) = krg[i];
                *(uint4*)(smc + nxt + 17408 + (vr + 32*i)*144 + vc*16) = vrg[i];
                float4 s4 = brg[i];
                uint32_t p0 = (e16(s4.y, lut, scale) << 16) | e16(s4.x, lut, scale);
                uint32_t p1 = (e16(s4.w, lut, scale) << 16) | e16(s4.z, lut, scale);
                uint32_t bb = nxt + 35840 + (kr + 16*i)*144 + bj*4;
                *(uint32_t*)(smc + bb + bc0*32) = p0;
                *(uint32_t*)(smc + bb + bc1*32) = p1;
            }
        }
        if (kb < NN/64 - 2) {
            const int k0n = (kb + 2) * 64;
            #pragma unroll
            for (int i = 0; i < 4; i++) {
                krg[i] = ksrc[(size_t)(k0n + kr + 16*i)*16 + kc];
                vrg[i] = vsrc[(size_t)(vr + 32*i)*1024 + (k0n >> 3) + vc];
                brg[i] = *(const float4*)(sp + (size_t)(q0 + kr + 16*i)*NN + k0n + kc*4);
            }
        }

        float S[2][8][4];
        #pragma unroll
        for (int mt = 0; mt < 2; mt++)
            #pragma unroll
            for (int j = 0; j < 8; j++)
                #pragma unroll
                for (int t = 0; t < 4; t++) S[mt][j][t] = 0.f;
        #pragma unroll
        for (int s = 0; s < 2; s++) {
            #pragma unroll
            for (int p = 0; p < 4; p++) {
                uint32_t kbf[4];
                ldsm4(kbf, kaddr0 + cur + p*(16*272) + s*32);
                #pragma unroll
                for (int mt = 0; mt < 2; mt++) {
                    mmaf16(S[mt][2*p],   qa[mt][s], kbf);
                    mmaf16(S[mt][2*p+1], qa[mt][s], kbf + 2);
                }
            }
        }

        uint32_t pk[2][4][4];
        #pragma unroll
        for (int mt = 0; mt < 2; mt++) {
            const uint32_t bmt = baddr0 + cur + mt*(16*144);
            uint32_t eL[4], eL2[4], eH[4], eH2[4];
            asm volatile("ld.shared.v4.b32 {%0,%1,%2,%3}, [%4];"
                : "=r"(eL[0]),"=r"(eL[1]),"=r"(eL[2]),"=r"(eL[3]) : "r"(bmt));
            asm volatile("ld.shared.v4.b32 {%0,%1,%2,%3}, [%4];"
                : "=r"(eL2[0]),"=r"(eL2[1]),"=r"(eL2[2]),"=r"(eL2[3]) : "r"(bmt + 16));
            asm volatile("ld.shared.v4.b32 {%0,%1,%2,%3}, [%4];"
                : "=r"(eH[0]),"=r"(eH[1]),"=r"(eH[2]),"=r"(eH[3]) : "r"(bmt + 8*144));
            asm volatile("ld.shared.v4.b32 {%0,%1,%2,%3}, [%4];"
                : "=r"(eH2[0]),"=r"(eH2[1]),"=r"(eH2[2]),"=r"(eH2[3]) : "r"(bmt + 8*144 + 16));
            float accL = 0.f, accH = 0.f;
            #pragma unroll
            for (int j = 0; j < 8; j++) {
                uint32_t ePL = (j < 4) ? eL[j] : eL2[j-4];
                uint32_t ePH = (j < 4) ? eH[j] : eH2[j-4];
                uint32_t u0 = ex2h2(packh2(fmaf(S[mt][j][1], L2E, MSH),
                                           fmaf(S[mt][j][0], L2E, MSH)));
                uint32_t u1 = ex2h2(packh2(fmaf(S[mt][j][3], L2E, MSH),
                                           fmaf(S[mt][j][2], L2E, MSH)));
                uint32_t pk0 = mulh2(u0, ePL);
                uint32_t pk1 = mulh2(u1, ePH);
                float2 f0 = h2f2(pk0);
                float2 f1 = h2f2(pk1);
                accL += f0.x + f0.y;
                accH += f1.x + f1.y;
                int s = j >> 1, o = (j & 1) * 2;
                pk[mt][s][o]     = pk0;
                pk[mt][s][o + 1] = pk1;
            }
            lsum[mt][0] += accL;
            lsum[mt][1] += accH;
        }

        #pragma unroll
        for (int s = 0; s < 4; s++) {
            uint32_t vb[8];
            ldsm4(vb,     vaddr0 + cur + s*32);
            ldsm4(vb + 4, vaddr0 + cur + 16*144 + s*32);
            #pragma unroll
            for (int mt = 0; mt < 2; mt++) {
                mmaf16(O[mt][0], pk[mt][s], vb);
                mmaf16(O[mt][1], pk[mt][s], vb + 2);
                mmaf16(O[mt][2], pk[mt][s], vb + 4);
                mmaf16(O[mt][3], pk[mt][s], vb + 6);
            }
        }
    }

    #pragma unroll
    for (int mt = 0; mt < 2; mt++) {
        float l0 = lsum[mt][0], l1 = lsum[mt][1];
        l0 += __shfl_xor_sync(0xffffffffu, l0, 1);
        l0 += __shfl_xor_sync(0xffffffffu, l0, 2);
        l1 += __shfl_xor_sync(0xffffffffu, l1, 1);
        l1 += __shfl_xor_sync(0xffffffffu, l1, 2);
        const float i0 = 1.0f / l0;
        const float i1 = 1.0f / l1;
        const int r  = q0 + qhf*32 + mt*16 + (lane >> 2);
        const int cb = h*32 + 2*(lane & 3);
        #pragma unroll
        for (int j = 0; j < 4; j++) {
            *(__half2*)(out + (size_t)r*128 + cb + 8*j)     = __floats2half2_rn(O[mt][j][0]*i0, O[mt][j][1]*i0);
            *(__half2*)(out + (size_t)(r+8)*128 + cb + 8*j) = __floats2half2_rn(O[mt][j][2]*i1, O[mt][j][3]*i1);
        }
    }
}

// ---------- log_softmax ----------
__global__ __launch_bounds__(256)
void logsoftmax_k(float* __restrict__ io)
{
    int row  = blockIdx.x * 8 + (threadIdx.x >> 5);
    int lane = threadIdx.x & 31;
    float* p = io + (size_t)row * OUTD;

    float a = p[lane];
    float b = (lane < 8) ? p[lane + 32] : -CUDART_INF_F;

    float mx = fmaxf(a, b);
    #pragma unroll
    for (int off = 16; off; off >>= 1)
        mx = fmaxf(mx, __shfl_xor_sync(0xffffffffu, mx, off));

    float e = __expf(a - mx) + ((lane < 8) ? __expf(b - mx) : 0.f);
    #pragma unroll
    for (int off = 16; off; off >>= 1)
        e += __shfl_xor_sync(0xffffffffu, e, off);

    float lse = mx + logf(e);
    p[lane] = a - lse;
    if (lane < 8) p[lane + 32] = b - lse;
}

// ---------- launch ----------
extern "C" void kernel_launch(void* const* d_in, const int* in_sizes, int n_in,
                              void* d_out, int out_size)
{
    (void)in_sizes; (void)n_in; (void)out_size;
    const float* x     = (const float*)d_in[0];
    const float* sp    = (const float*)d_in[2];
    const float* W_in  = (const float*)d_in[3];
    const float* b_in  = (const float*)d_in[4];
    const float* ipw   = (const float*)d_in[5];
    const float* ipb   = (const float*)d_in[6];
    const float* opw   = (const float*)d_in[7];
    const float* opb   = (const float*)d_in[8];
    const float* Wout  = (const float*)d_in[9];
    const float* bout  = (const float*)d_in[10];
    const float* scale = (const float*)d_in[11];
    float* out = (float*)d_out;

    float *gh, *gh2;
    __half *gh16, *gq, *gk, *gv, *gao, *gipw16, *gopw16;
    cudaGetSymbolAddress((void**)&gh,     g_h);
    cudaGetSymbolAddress((void**)&gh2,    g_h2);
    cudaGetSymbolAddress((void**)&gh16,   g_h16);
    cudaGetSymbolAddress((void**)&gq,     g_qh);
    cudaGetSymbolAddress((void**)&gk,     g_kh);
    cudaGetSymbolAddress((void**)&gv,     g_vt);
    cudaGetSymbolAddress((void**)&gao,    g_ao);
    cudaGetSymbolAddress((void**)&gipw16, g_ipw16);
    cudaGetSymbolAddress((void**)&gopw16, g_opw16);

    cudaFuncSetAttribute(gemm_k,   cudaFuncAttributeMaxDynamicSharedMemorySize, GEMM_SMEM_BYTES);
    cudaFuncSetAttribute(gemm16_k, cudaFuncAttributeMaxDynamicSharedMemorySize, G16_SMEM);
    cudaFuncSetAttribute(attn_k,   cudaFuncAttributeMaxDynamicSharedMemorySize, ATTN_SMEM);

    wcvt_k<<<64, 256>>>(ipw, opw, gipw16, gopw16);
    gemm_k<<<dim3(NN/64, 2), 256, GEMM_SMEM_BYTES>>>(x, W_in, b_in, gh, HID, 3, gh16);
    gemm16_k<<<dim3(NN/128, 6), 256, G16_SMEM>>>(gh16, gipw16, ipb, nullptr, nullptr, 2,
                                                 gq, gk, gv);
    attn_k<<<NN/64, 256, ATTN_SMEM>>>(gq, gk, gv, sp, scale, gao);
    gemm16_k<<<dim3(NN/128, 2), 256, G16_SMEM>>>(gao, gopw16, opb, gh, gh2, 1,
                                                 nullptr, nullptr, nullptr);
    gemm_k<<<dim3(NN/64, 1), 256, GEMM_SMEM_BYTES>>>(gh2, Wout, bout, out, OUTD, 0, nullptr);
    logsoftmax_k<<<NN/8, 256>>>(out);
}

// round 13
// speedup vs baseline: 1.0222x; 1.0222x over previous
#include <cuda_runtime.h>
#include <cuda_fp16.h>
#include <math_constants.h>
#include <cstdint>

#define NN    8192
#define HID   128
#define OUTD  40
#define RSQRT_HD 0.17677669529663687f
#define L2E      1.4426950408889634f
#define MSH      (-4.0f * 1.4426950408889634f)

__device__ __align__(16) float  g_h   [NN * HID];
__device__ __align__(16) __half g_h16 [NN * HID];
__device__ __align__(16) __half g_qh  [NN * HID];
__device__ __align__(16) __half g_kh  [NN * HID];
__device__ __align__(16) __half g_vt  [HID * NN];
__device__ __align__(16) __half g_ao  [NN * HID];
__device__ __align__(16) float  g_h2  [NN * HID];
__device__ __align__(16) __half g_ipw16[3*HID*HID];
__device__ __align__(16) __half g_opw16[HID*HID];

__device__ __forceinline__ uint32_t smem_u32(const void* p){
    uint32_t a;
    asm("{ .reg .u64 t; cvta.to.shared.u64 t, %1; cvt.u32.u64 %0, t; }" : "=r"(a) : "l"(p));
    return a;
}
__device__ __forceinline__ void ldsm4(uint32_t r[4], uint32_t addr){
    asm volatile("ldmatrix.sync.aligned.m8n8.x4.shared.b16 {%0,%1,%2,%3}, [%4];"
        : "=r"(r[0]), "=r"(r[1]), "=r"(r[2]), "=r"(r[3]) : "r"(addr));
}
__device__ __forceinline__ void mmaf16(float c[4], const uint32_t a[4], const uint32_t b[2]){
    asm volatile("mma.sync.aligned.m16n8k16.row.col.f32.f16.f16.f32 "
        "{%0,%1,%2,%3}, {%4,%5,%6,%7}, {%8,%9}, {%0,%1,%2,%3};"
        : "+f"(c[0]), "+f"(c[1]), "+f"(c[2]), "+f"(c[3])
        : "r"(a[0]), "r"(a[1]), "r"(a[2]), "r"(a[3]), "r"(b[0]), "r"(b[1]));
}
__device__ __forceinline__ uint32_t packh2(float hi, float lo){
    uint32_t r; asm("cvt.rn.f16x2.f32 %0, %1, %2;" : "=r"(r) : "f"(hi), "f"(lo)); return r;
}
__device__ __forceinline__ uint32_t ex2h2(uint32_t a){
    uint32_t d; asm("ex2.approx.f16x2 %0, %1;" : "=r"(d) : "r"(a)); return d;
}
__device__ __forceinline__ uint32_t mulh2(uint32_t a, uint32_t b){
    uint32_t d; asm("mul.rn.f16x2 %0, %1, %2;" : "=r"(d) : "r"(a), "r"(b)); return d;
}
__device__ __forceinline__ uint32_t e16(float s, uint32_t lutaddr, float scale){
    int idx = __float2int_rn(s);
    uint32_t h;
    if (__int2float_rn(idx) == s && idx >= 0 && idx <= 10) {
        asm volatile("ld.shared.u16 %0, [%1];" : "=r"(h) : "r"(lutaddr + idx*2));
    } else {
        float ss = (isnan(s) || isinf(s)) ? -1.0f : s;
        float r = __fdividef(1.0f, ss);
        if (isnan(r) || isinf(r)) r = 0.0f;
        float e = exp2f(fmaf(scale, r, -scale) * L2E);
        h = (uint32_t)__half_as_ushort(__float2half_rn(e));
    }
    return h;
}

// ---------- weight convert ----------
__global__ __launch_bounds__(256)
void wcvt_k(const float* __restrict__ a, const float* __restrict__ b,
            __half* __restrict__ a16, __half* __restrict__ b16)
{
    int idx = blockIdx.x*256 + threadIdx.x;
    for (int i = idx; i < 3*HID*HID; i += 16384) a16[i] = __float2half_rn(a[i]);
    for (int i = idx; i < HID*HID;   i += 16384) b16[i] = __float2half_rn(b[i]);
}

// ---------- fp32 GEMM (gemm1 mode3: fp32 + f16 copy; Wout mode0) ----------
#define GEMM_SMEM_BYTES ((2*128*64 + 64*132) * 4)

__global__ __launch_bounds__(256, 2)
void gemm_k(const float* __restrict__ A, const float* __restrict__ W,
            const float* __restrict__ bias, float* __restrict__ C,
            int CO, int mode, __half* __restrict__ c16)
{
    extern __shared__ float sm[];
    float* At  = sm;
    float* Wt  = sm + 128*64;
    float* Stg = sm + 2*128*64;
    const int r0  = blockIdx.x * 64;
    const int c0  = blockIdx.y * 64;
    const int tid = threadIdx.x;

    {
        const float4* Af4 = (const float4*)(A + (size_t)r0 * 128);
        float4* Sf4 = (float4*)Stg;
        #pragma unroll
        for (int i = 0; i < 8; i++) {
            int idx = tid + 256*i;
            int r = idx >> 5, d4 = idx & 31;
            Sf4[r*33 + d4] = Af4[r*32 + d4];
        }
    }
    __syncthreads();
    {
        #pragma unroll
        for (int i = 0; i < 8; i++) {
            int idx = tid + 256*i;
            int r = idx & 63, d4 = idx >> 6;
            float4 v = *(const float4*)&Stg[r*132 + d4*4];
            At[(4*d4+0)*64 + r] = v.x; At[(4*d4+1)*64 + r] = v.y;
            At[(4*d4+2)*64 + r] = v.z; At[(4*d4+3)*64 + r] = v.w;
        }
    }
    __syncthreads();
    {
        const float4* Wf4 = (const float4*)W;
        float4* Sf4 = (float4*)Stg;
        #pragma unroll
        for (int i = 0; i < 8; i++) {
            int idx = tid + 256*i;
            int c = idx >> 5, d4 = idx & 31;
            float4 v = make_float4(0.f,0.f,0.f,0.f);
            if (c0 + c < CO) v = Wf4[(size_t)(c0 + c)*32 + d4];
            Sf4[c*33 + d4] = v;
        }
    }
    __syncthreads();
    {
        #pragma unroll
        for (int i = 0; i < 8; i++) {
            int idx = tid + 256*i;
            int c = idx & 63, d4 = idx >> 6;
            float4 v = *(const float4*)&Stg[c*132 + d4*4];
            Wt[(4*d4+0)*64 + c] = v.x; Wt[(4*d4+1)*64 + c] = v.y;
            Wt[(4*d4+2)*64 + c] = v.z; Wt[(4*d4+3)*64 + c] = v.w;
        }
    }
    __syncthreads();

    const int tr = tid >> 4;
    const int tc = tid & 15;
    float acc[4][4];
    #pragma unroll
    for (int i = 0; i < 4; i++)
        #pragma unroll
        for (int j = 0; j < 4; j++) acc[i][j] = 0.f;

    #pragma unroll 8
    for (int d = 0; d < 128; d++) {
        float4 a = *(const float4*)&At[d*64 + tr*4];
        float4 w = *(const float4*)&Wt[d*64 + tc*4];
        float av[4] = {a.x, a.y, a.z, a.w};
        float wv[4] = {w.x, w.y, w.z, w.w};
        #pragma unroll
        for (int i = 0; i < 4; i++)
            #pragma unroll
            for (int j = 0; j < 4; j++)
                acc[i][j] = fmaf(av[i], wv[j], acc[i][j]);
    }

    #pragma unroll
    for (int i = 0; i < 4; i++) {
        int r = r0 + tr*4 + i;
        #pragma unroll
        for (int j = 0; j < 4; j++) {
            int c = c0 + tc*4 + j;
            if (c < CO) {
                float v = acc[i][j] + bias[c];
                C[(size_t)r*CO + c] = v;
                if (mode == 3) c16[(size_t)r*128 + c] = __float2half_rn(v);
            }
        }
    }
}

// ---------- f16 HMMA GEMM (proven in R12): mode2 qkv epilogue, mode1 residual-relu ----------
#define G16_AS   0
#define G16_WS   34816
#define G16_SMEM 52224

__global__ __launch_bounds__(256, 2)
void gemm16_k(const __half* __restrict__ A, const __half* __restrict__ W,
              const float* __restrict__ bias, const float* __restrict__ R,
              float* __restrict__ C, int mode,
              __half* __restrict__ qh, __half* __restrict__ kh, __half* __restrict__ vt)
{
    extern __shared__ char smc[];
    const uint32_t sb = smem_u32(smc);
    const int tid  = threadIdx.x;
    const int lane = tid & 31;
    const int wid  = tid >> 5;
    const int r0   = blockIdx.x * 128;
    const int c0   = blockIdx.y * 64;

    {
        const uint4* Asrc = (const uint4*)A;
        #pragma unroll
        for (int i = 0; i < 8; i++) {
            int idx = tid + 256*i;
            int r = idx >> 4, c = idx & 15;
            *(uint4*)(smc + G16_AS + r*272 + c*16) = Asrc[(size_t)(r0 + r)*16 + c];
        }
        const uint4* Wsrc = (const uint4*)W;
        #pragma unroll
        for (int i = 0; i < 4; i++) {
            int idx = tid + 256*i;
            int r = idx >> 4, c = idx & 15;
            *(uint4*)(smc + G16_WS + r*272 + c*16) = Wsrc[(size_t)(c0 + r)*16 + c];
        }
    }
    __syncthreads();

    const int mrow = (wid >> 1) * 32;
    const int ncol = (wid & 1) * 32;
    const uint32_t aaddr = sb + G16_AS + (mrow + (lane & 15))*272 + ((lane >> 4) & 1)*16;
    const uint32_t baddr = sb + G16_WS + (ncol + (lane & 7) + ((lane >> 4) & 1)*8)*272
                           + ((lane >> 3) & 1)*16;

    float acc[2][4][4];
    #pragma unroll
    for (int mt = 0; mt < 2; mt++)
        #pragma unroll
        for (int nt = 0; nt < 4; nt++)
            #pragma unroll
            for (int e = 0; e < 4; e++) acc[mt][nt][e] = 0.f;

    #pragma unroll
    for (int k = 0; k < 8; k++) {
        uint32_t af[2][4], bf[2][4];
        ldsm4(af[0], aaddr + k*32);
        ldsm4(af[1], aaddr + 16*272 + k*32);
        ldsm4(bf[0], baddr + k*32);
        ldsm4(bf[1], baddr + 16*272 + k*32);
        #pragma unroll
        for (int mt = 0; mt < 2; mt++)
            #pragma unroll
            for (int p = 0; p < 2; p++) {
                mmaf16(acc[mt][2*p],   af[mt], bf[p]);
                mmaf16(acc[mt][2*p+1], af[mt], bf[p] + 2);
            }
    }

    const int rb = r0 + mrow + (lane >> 2);
    const int cb = c0 + ncol + 2*(lane & 3);
    #pragma unroll
    for (int mt = 0; mt < 2; mt++) {
        #pragma unroll
        for (int nt = 0; nt < 4; nt++) {
            int r = rb + mt*16;
            int c = cb + nt*8;
            float v0 = acc[mt][nt][0] + bias[c];
            float v1 = acc[mt][nt][1] + bias[c+1];
            float v2 = acc[mt][nt][2] + bias[c];
            float v3 = acc[mt][nt][3] + bias[c+1];
            if (mode == 2) {
                if (c < 128) {
                    *(__half2*)(qh + (size_t)r*128 + c)     = __floats2half2_rn(v0*RSQRT_HD, v1*RSQRT_HD);
                    *(__half2*)(qh + (size_t)(r+8)*128 + c) = __floats2half2_rn(v2*RSQRT_HD, v3*RSQRT_HD);
                } else if (c < 256) {
                    *(__half2*)(kh + (size_t)r*128 + (c-128))     = __floats2half2_rn(v0, v1);
                    *(__half2*)(kh + (size_t)(r+8)*128 + (c-128)) = __floats2half2_rn(v2, v3);
                } else {
                    vt[(size_t)(c-256)*NN + r]       = __float2half_rn(v0);
                    vt[(size_t)(c-255)*NN + r]       = __float2half_rn(v1);
                    vt[(size_t)(c-256)*NN + (r+8)]   = __float2half_rn(v2);
                    vt[(size_t)(c-255)*NN + (r+8)]   = __float2half_rn(v3);
                }
            } else {
                float2 R0 = *(const float2*)(R + (size_t)r*128 + c);
                float2 R1 = *(const float2*)(R + (size_t)(r+8)*128 + c);
                *(float2*)(C + (size_t)r*128 + c)     = make_float2(R0.x + fmaxf(v0,0.f), R0.y + fmaxf(v1,0.f));
                *(float2*)(C + (size_t)(r+8)*128 + c) = make_float2(R1.x + fmaxf(v2,0.f), R1.y + fmaxf(v3,0.f));
            }
        }
    }
}

// ---------- flash attention: R11 structure; l computed via ones-column MMA ----------
#define STAGE     45056
#define LUT_OFF   90112
#define ATTN_SMEM 90240

__global__ __launch_bounds__(256, 1)
void attn_k(const __half* __restrict__ qh_g, const __half* __restrict__ kh_g,
            const __half* __restrict__ vt_g, const float* __restrict__ sp,
            const float* __restrict__ scale_ptr, __half* __restrict__ out)
{
    extern __shared__ char smc[];
    const uint32_t sb = smem_u32(smc);
    const int tid  = threadIdx.x;
    const int lane = tid & 31;
    const int wid  = tid >> 5;
    const int h    = wid >> 1;
    const int qhf  = wid & 1;
    const int q0   = blockIdx.x * 64;
    const float scale = scale_ptr[0];
    const uint32_t lut = sb + LUT_OFF;

    if (tid <= 10) {
        float e = (tid == 0) ? expf(-scale) : expf(scale / (float)tid - scale);
        uint32_t hb = (uint32_t)__half_as_ushort(__float2half_rn(e));
        asm volatile("st.shared.u16 [%0], %1;" :: "r"(lut + tid*2), "r"(hb));
    }
    {
        const uint4* qsrc = (const uint4*)(qh_g + (size_t)q0 * 128);
        #pragma unroll
        for (int i = 0; i < 4; i++) {
            int idx = tid + 256*i;
            int r = idx >> 4, c = idx & 15;
            *(uint4*)(smc + STAGE + r*272 + c*16) = qsrc[r*16 + c];
        }
    }
    __syncthreads();
    uint32_t qa[2][2][4];
    #pragma unroll
    for (int mt = 0; mt < 2; mt++) {
        uint32_t qaddr = sb + STAGE + (qhf*32 + mt*16 + (lane & 15))*272
                         + (h*4 + (lane >> 4))*16;
        ldsm4(qa[mt][0], qaddr);
        ldsm4(qa[mt][1], qaddr + 32);
    }

    const uint32_t kaddr0 = sb + ((lane & 7) + ((lane >> 4) & 1)*8)*272
                            + h*64 + ((lane >> 3) & 1)*16;
    const uint32_t vaddr0 = sb + 17408 + (h*32 + (lane & 7) + ((lane >> 4) & 1)*8)*144
                            + ((lane >> 3) & 1)*16;
    const uint32_t baddr0 = sb + 35840 + (qhf*32 + (lane >> 2))*144 + (lane & 3)*32;

    float O[2][4][4];
    #pragma unroll
    for (int mt = 0; mt < 2; mt++)
        #pragma unroll
        for (int i = 0; i < 4; i++)
            #pragma unroll
            for (int j = 0; j < 4; j++) O[mt][i][j] = 0.f;
    float lacc[2][4];                          // l via ones-MMA (fp32 exact sums of f16 p)
    #pragma unroll
    for (int mt = 0; mt < 2; mt++)
        #pragma unroll
        for (int e = 0; e < 4; e++) lacc[mt][e] = 0.f;
    const uint32_t ones2[2] = {0x3C003C00u, 0x3C003C00u};

    const uint4* ksrc = (const uint4*)kh_g;
    const uint4* vsrc = (const uint4*)vt_g;

    const int kr = tid >> 4, kc = tid & 15;
    const int vr = tid >> 3, vc = tid & 7;
    const int bj  = kc >> 1;
    const int bc0 = (2*kc) & 3, bc1 = (2*kc + 1) & 3;

    uint4  krg[4], vrg[4];
    float4 brg[4];
    #pragma unroll
    for (int i = 0; i < 4; i++) {
        krg[i] = ksrc[(size_t)(kr + 16*i)*16 + kc];
        vrg[i] = vsrc[(size_t)(vr + 32*i)*1024 + vc];
        brg[i] = *(const float4*)(sp + (size_t)(q0 + kr + 16*i)*NN + kc*4);
    }
    {
        #pragma unroll
        for (int i = 0; i < 4; i++) {
            *(uint4*)(smc + (kr + 16*i)*272 + kc*16) = krg[i];
            *(uint4*)(smc + 17408 + (vr + 32*i)*144 + vc*16) = vrg[i];
            float4 s4 = brg[i];
            uint32_t p0 = (e16(s4.y, lut, scale) << 16) | e16(s4.x, lut, scale);
            uint32_t p1 = (e16(s4.w, lut, scale) << 16) | e16(s4.z, lut, scale);
            uint32_t bb = 35840 + (kr + 16*i)*144 + bj*4;
            *(uint32_t*)(smc + bb + bc0*32) = p0;
            *(uint32_t*)(smc + bb + bc1*32) = p1;
        }
        #pragma unroll
        for (int i = 0; i < 4; i++) {
            krg[i] = ksrc[(size_t)(64 + kr + 16*i)*16 + kc];
            vrg[i] = vsrc[(size_t)(vr + 32*i)*1024 + 8 + vc];
            brg[i] = *(const float4*)(sp + (size_t)(q0 + kr + 16*i)*NN + 64 + kc*4);
        }
    }

    for (int kb = 0; kb < NN/64; kb++) {
        __syncthreads();
        const uint32_t cur = (kb & 1) * STAGE;
        const uint32_t nxt = ((kb + 1) & 1) * STAGE;

        if (kb < NN/64 - 1) {
            #pragma unroll
            for (int i = 0; i < 4; i++) {
                *(uint4*)(smc + nxt + (kr + 16*i)*272 + kc*16) = krg[i];
                *(uint4*)(smc + nxt + 17408 + (vr + 32*i)*144 + vc*16) = vrg[i];
                float4 s4 = brg[i];
                uint32_t p0 = (e16(s4.y, lut, scale) << 16) | e16(s4.x, lut, scale);
                uint32_t p1 = (e16(s4.w, lut, scale) << 16) | e16(s4.z, lut, scale);
                uint32_t bb = nxt + 35840 + (kr + 16*i)*144 + bj*4;
                *(uint32_t*)(smc + bb + bc0*32) = p0;
                *(uint32_t*)(smc + bb + bc1*32) = p1;
            }
        }
        if (kb < NN/64 - 2) {
            const int k0n = (kb + 2) * 64;
            #pragma unroll
            for (int i = 0; i < 4; i++) {
                krg[i] = ksrc[(size_t)(k0n + kr + 16*i)*16 + kc];
                vrg[i] = vsrc[(size_t)(vr + 32*i)*1024 + (k0n >> 3) + vc];
                brg[i] = *(const float4*)(sp + (size_t)(q0 + kr + 16*i)*NN + k0n + kc*4);
            }
        }

        float S[2][8][4];
        #pragma unroll
        for (int mt = 0; mt < 2; mt++)
            #pragma unroll
            for (int j = 0; j < 8; j++)
                #pragma unroll
                for (int t = 0; t < 4; t++) S[mt][j][t] = 0.f;
        #pragma unroll
        for (int s = 0; s < 2; s++) {
            #pragma unroll
            for (int p = 0; p < 4; p++) {
                uint32_t kbf[4];
                ldsm4(kbf, kaddr0 + cur + p*(16*272) + s*32);
                #pragma unroll
                for (int mt = 0; mt < 2; mt++) {
                    mmaf16(S[mt][2*p],   qa[mt][s], kbf);
                    mmaf16(S[mt][2*p+1], qa[mt][s], kbf + 2);
                }
            }
        }

        // softmax: p = ex2((S-4)*L2E) * E' ; no scalar l accumulation (ones-MMA below)
        uint32_t pk[2][4][4];
        #pragma unroll
        for (int mt = 0; mt < 2; mt++) {
            const uint32_t bmt = baddr0 + cur + mt*(16*144);
            uint32_t eL[4], eL2[4], eH[4], eH2[4];
            asm volatile("ld.shared.v4.b32 {%0,%1,%2,%3}, [%4];"
                : "=r"(eL[0]),"=r"(eL[1]),"=r"(eL[2]),"=r"(eL[3]) : "r"(bmt));
            asm volatile("ld.shared.v4.b32 {%0,%1,%2,%3}, [%4];"
                : "=r"(eL2[0]),"=r"(eL2[1]),"=r"(eL2[2]),"=r"(eL2[3]) : "r"(bmt + 16));
            asm volatile("ld.shared.v4.b32 {%0,%1,%2,%3}, [%4];"
                : "=r"(eH[0]),"=r"(eH[1]),"=r"(eH[2]),"=r"(eH[3]) : "r"(bmt + 8*144));
            asm volatile("ld.shared.v4.b32 {%0,%1,%2,%3}, [%4];"
                : "=r"(eH2[0]),"=r"(eH2[1]),"=r"(eH2[2]),"=r"(eH2[3]) : "r"(bmt + 8*144 + 16));
            #pragma unroll
            for (int j = 0; j < 8; j++) {
                uint32_t ePL = (j < 4) ? eL[j] : eL2[j-4];
                uint32_t ePH = (j < 4) ? eH[j] : eH2[j-4];
                uint32_t u0 = ex2h2(packh2(fmaf(S[mt][j][1], L2E, MSH),
                                           fmaf(S[mt][j][0], L2E, MSH)));
                uint32_t u1 = ex2h2(packh2(fmaf(S[mt][j][3], L2E, MSH),
                                           fmaf(S[mt][j][2], L2E, MSH)));
                int s = j >> 1, o = (j & 1) * 2;
                pk[mt][s][o]     = mulh2(u0, ePL);
                pk[mt][s][o + 1] = mulh2(u1, ePH);
            }
        }

        // O += P V ; l += P·1 (ones B-fragment: every lane's c[0]/c[2] = its row sum)
        #pragma unroll
        for (int s = 0; s < 4; s++) {
            uint32_t vb[8];
            ldsm4(vb,     vaddr0 + cur + s*32);
            ldsm4(vb + 4, vaddr0 + cur + 16*144 + s*32);
            #pragma unroll
            for (int mt = 0; mt < 2; mt++) {
                mmaf16(O[mt][0], pk[mt][s], vb);
                mmaf16(O[mt][1], pk[mt][s], vb + 2);
                mmaf16(O[mt][2], pk[mt][s], vb + 4);
                mmaf16(O[mt][3], pk[mt][s], vb + 6);
                mmaf16(lacc[mt], pk[mt][s], ones2);
            }
        }
    }

    // finalize: lacc[mt][0] = row-r sum, lacc[mt][2] = row-(r+8) sum (no shuffles needed)
    #pragma unroll
    for (int mt = 0; mt < 2; mt++) {
        const float i0 = 1.0f / lacc[mt][0];
        const float i1 = 1.0f / lacc[mt][2];
        const int r  = q0 + qhf*32 + mt*16 + (lane >> 2);
        const int cb = h*32 + 2*(lane & 3);
        #pragma unroll
        for (int j = 0; j < 4; j++) {
            *(__half2*)(out + (size_t)r*128 + cb + 8*j)     = __floats2half2_rn(O[mt][j][0]*i0, O[mt][j][1]*i0);
            *(__half2*)(out + (size_t)(r+8)*128 + cb + 8*j) = __floats2half2_rn(O[mt][j][2]*i1, O[mt][j][3]*i1);
        }
    }
}

// ---------- log_softmax ----------
__global__ __launch_bounds__(256)
void logsoftmax_k(float* __restrict__ io)
{
    int row  = blockIdx.x * 8 + (threadIdx.x >> 5);
    int lane = threadIdx.x & 31;
    float* p = io + (size_t)row * OUTD;

    float a = p[lane];
    float b = (lane < 8) ? p[lane + 32] : -CUDART_INF_F;

    float mx = fmaxf(a, b);
    #pragma unroll
    for (int off = 16; off; off >>= 1)
        mx = fmaxf(mx, __shfl_xor_sync(0xffffffffu, mx, off));

    float e = __expf(a - mx) + ((lane < 8) ? __expf(b - mx) : 0.f);
    #pragma unroll
    for (int off = 16; off; off >>= 1)
        e += __shfl_xor_sync(0xffffffffu, e, off);

    float lse = mx + logf(e);
    p[lane] = a - lse;
    if (lane < 8) p[lane + 32] = b - lse;
}

// ---------- launch ----------
extern "C" void kernel_launch(void* const* d_in, const int* in_sizes, int n_in,
                              void* d_out, int out_size)
{
    (void)in_sizes; (void)n_in; (void)out_size;
    const float* x     = (const float*)d_in[0];
    const float* sp    = (const float*)d_in[2];
    const float* W_in  = (const float*)d_in[3];
    const float* b_in  = (const float*)d_in[4];
    const float* ipw   = (const float*)d_in[5];
    const float* ipb   = (const float*)d_in[6];
    const float* opw   = (const float*)d_in[7];
    const float* opb   = (const float*)d_in[8];
    const float* Wout  = (const float*)d_in[9];
    const float* bout  = (const float*)d_in[10];
    const float* scale = (const float*)d_in[11];
    float* out = (float*)d_out;

    float *gh, *gh2;
    __half *gh16, *gq, *gk, *gv, *gao, *gipw16, *gopw16;
    cudaGetSymbolAddress((void**)&gh,     g_h);
    cudaGetSymbolAddress((void**)&gh2,    g_h2);
    cudaGetSymbolAddress((void**)&gh16,   g_h16);
    cudaGetSymbolAddress((void**)&gq,     g_qh);
    cudaGetSymbolAddress((void**)&gk,     g_kh);
    cudaGetSymbolAddress((void**)&gv,     g_vt);
    cudaGetSymbolAddress((void**)&gao,    g_ao);
    cudaGetSymbolAddress((void**)&gipw16, g_ipw16);
    cudaGetSymbolAddress((void**)&gopw16, g_opw16);

    cudaFuncSetAttribute(gemm_k,   cudaFuncAttributeMaxDynamicSharedMemorySize, GEMM_SMEM_BYTES);
    cudaFuncSetAttribute(gemm16_k, cudaFuncAttributeMaxDynamicSharedMemorySize, G16_SMEM);
    cudaFuncSetAttribute(attn_k,   cudaFuncAttributeMaxDynamicSharedMemorySize, ATTN_SMEM);

    wcvt_k<<<64, 256>>>(ipw, opw, gipw16, gopw16);
    gemm_k<<<dim3(NN/64, 2), 256, GEMM_SMEM_BYTES>>>(x, W_in, b_in, gh, HID, 3, gh16);
    gemm16_k<<<dim3(NN/128, 6), 256, G16_SMEM>>>(gh16, gipw16, ipb, nullptr, nullptr, 2,
                                                 gq, gk, gv);
    attn_k<<<NN/64, 256, ATTN_SMEM>>>(gq, gk, gv, sp, scale, gao);
    gemm16_k<<<dim3(NN/128, 2), 256, G16_SMEM>>>(gao, gopw16, opb, gh, gh2, 1,
                                                 nullptr, nullptr, nullptr);
    gemm_k<<<dim3(NN/64, 1), 256, GEMM_SMEM_BYTES>>>(gh2, Wout, bout, out, OUTD, 0, nullptr);
    logsoftmax_k<<<NN/8, 256>>>(out);
}

// round 14
// speedup vs baseline: 1.1081x; 1.0841x over previous
#include <cuda_runtime.h>
#include <cuda_fp16.h>
#include <math_constants.h>
#include <cstdint>

#define NN    8192
#define HID   128
#define OUTD  40
#define RSQRT_HD 0.17677669529663687f
#define L2E      1.4426950408889634f
#define MSH      (-4.0f * 1.4426950408889634f)

__device__ __align__(16) float  g_h   [NN * HID];
__device__ __align__(16) __half g_h16 [NN * HID];
__device__ __align__(16) __half g_qh  [NN * HID];
__device__ __align__(16) __half g_kh  [NN * HID];
__device__ __align__(16) __half g_vt  [HID * NN];
__device__ __align__(16) __half g_ao  [NN * HID];
__device__ __align__(16) float  g_h2  [NN * HID];
__device__ __align__(16) __half g_ipw16[3*HID*HID];
__device__ __align__(16) __half g_opw16[HID*HID];

__device__ __forceinline__ uint32_t smem_u32(const void* p){
    uint32_t a;
    asm("{ .reg .u64 t; cvta.to.shared.u64 t, %1; cvt.u32.u64 %0, t; }" : "=r"(a) : "l"(p));
    return a;
}
__device__ __forceinline__ void ldsm4(uint32_t r[4], uint32_t addr){
    asm volatile("ldmatrix.sync.aligned.m8n8.x4.shared.b16 {%0,%1,%2,%3}, [%4];"
        : "=r"(r[0]), "=r"(r[1]), "=r"(r[2]), "=r"(r[3]) : "r"(addr));
}
__device__ __forceinline__ void mmaf16(float c[4], const uint32_t a[4], const uint32_t b[2]){
    asm volatile("mma.sync.aligned.m16n8k16.row.col.f32.f16.f16.f32 "
        "{%0,%1,%2,%3}, {%4,%5,%6,%7}, {%8,%9}, {%0,%1,%2,%3};"
        : "+f"(c[0]), "+f"(c[1]), "+f"(c[2]), "+f"(c[3])
        : "r"(a[0]), "r"(a[1]), "r"(a[2]), "r"(a[3]), "r"(b[0]), "r"(b[1]));
}
__device__ __forceinline__ uint32_t packh2(float hi, float lo){
    uint32_t r; asm("cvt.rn.f16x2.f32 %0, %1, %2;" : "=r"(r) : "f"(hi), "f"(lo)); return r;
}
__device__ __forceinline__ uint32_t ex2h2(uint32_t a){
    uint32_t d; asm("ex2.approx.f16x2 %0, %1;" : "=r"(d) : "r"(a)); return d;
}
__device__ __forceinline__ uint32_t mulh2(uint32_t a, uint32_t b){
    uint32_t d; asm("mul.rn.f16x2 %0, %1, %2;" : "=r"(d) : "r"(a), "r"(b)); return d;
}
__device__ __forceinline__ uint32_t e16(float s, uint32_t lutaddr, float scale){
    int idx = __float2int_rn(s);
    uint32_t h;
    if (__int2float_rn(idx) == s && idx >= 0 && idx <= 10) {
        asm volatile("ld.shared.u16 %0, [%1];" : "=r"(h) : "r"(lutaddr + idx*2));
    } else {
        float ss = (isnan(s) || isinf(s)) ? -1.0f : s;
        float r = __fdividef(1.0f, ss);
        if (isnan(r) || isinf(r)) r = 0.0f;
        float e = exp2f(fmaf(scale, r, -scale) * L2E);
        h = (uint32_t)__half_as_ushort(__float2half_rn(e));
    }
    return h;
}

// ---------- weight convert ----------
__global__ __launch_bounds__(256)
void wcvt_k(const float* __restrict__ a, const float* __restrict__ b,
            __half* __restrict__ a16, __half* __restrict__ b16)
{
    int idx = blockIdx.x*256 + threadIdx.x;
    for (int i = idx; i < 3*HID*HID; i += 16384) a16[i] = __float2half_rn(a[i]);
    for (int i = idx; i < HID*HID;   i += 16384) b16[i] = __float2half_rn(b[i]);
}

// ---------- fp32 GEMM (gemm1 mode3: fp32 + f16 copy; Wout mode0) ----------
#define GEMM_SMEM_BYTES ((2*128*64 + 64*132) * 4)

__global__ __launch_bounds__(256, 2)
void gemm_k(const float* __restrict__ A, const float* __restrict__ W,
            const float* __restrict__ bias, float* __restrict__ C,
            int CO, int mode, __half* __restrict__ c16)
{
    extern __shared__ float sm[];
    float* At  = sm;
    float* Wt  = sm + 128*64;
    float* Stg = sm + 2*128*64;
    const int r0  = blockIdx.x * 64;
    const int c0  = blockIdx.y * 64;
    const int tid = threadIdx.x;

    {
        const float4* Af4 = (const float4*)(A + (size_t)r0 * 128);
        float4* Sf4 = (float4*)Stg;
        #pragma unroll
        for (int i = 0; i < 8; i++) {
            int idx = tid + 256*i;
            int r = idx >> 5, d4 = idx & 31;
            Sf4[r*33 + d4] = Af4[r*32 + d4];
        }
    }
    __syncthreads();
    {
        #pragma unroll
        for (int i = 0; i < 8; i++) {
            int idx = tid + 256*i;
            int r = idx & 63, d4 = idx >> 6;
            float4 v = *(const float4*)&Stg[r*132 + d4*4];
            At[(4*d4+0)*64 + r] = v.x; At[(4*d4+1)*64 + r] = v.y;
            At[(4*d4+2)*64 + r] = v.z; At[(4*d4+3)*64 + r] = v.w;
        }
    }
    __syncthreads();
    {
        const float4* Wf4 = (const float4*)W;
        float4* Sf4 = (float4*)Stg;
        #pragma unroll
        for (int i = 0; i < 8; i++) {
            int idx = tid + 256*i;
            int c = idx >> 5, d4 = idx & 31;
            float4 v = make_float4(0.f,0.f,0.f,0.f);
            if (c0 + c < CO) v = Wf4[(size_t)(c0 + c)*32 + d4];
            Sf4[c*33 + d4] = v;
        }
    }
    __syncthreads();
    {
        #pragma unroll
        for (int i = 0; i < 8; i++) {
            int idx = tid + 256*i;
            int c = idx & 63, d4 = idx >> 6;
            float4 v = *(const float4*)&Stg[c*132 + d4*4];
            Wt[(4*d4+0)*64 + c] = v.x; Wt[(4*d4+1)*64 + c] = v.y;
            Wt[(4*d4+2)*64 + c] = v.z; Wt[(4*d4+3)*64 + c] = v.w;
        }
    }
    __syncthreads();

    const int tr = tid >> 4;
    const int tc = tid & 15;
    float acc[4][4];
    #pragma unroll
    for (int i = 0; i < 4; i++)
        #pragma unroll
        for (int j = 0; j < 4; j++) acc[i][j] = 0.f;

    #pragma unroll 8
    for (int d = 0; d < 128; d++) {
        float4 a = *(const float4*)&At[d*64 + tr*4];
        float4 w = *(const float4*)&Wt[d*64 + tc*4];
        float av[4] = {a.x, a.y, a.z, a.w};
        float wv[4] = {w.x, w.y, w.z, w.w};
        #pragma unroll
        for (int i = 0; i < 4; i++)
            #pragma unroll
            for (int j = 0; j < 4; j++)
                acc[i][j] = fmaf(av[i], wv[j], acc[i][j]);
    }

    #pragma unroll
    for (int i = 0; i < 4; i++) {
        int r = r0 + tr*4 + i;
        #pragma unroll
        for (int j = 0; j < 4; j++) {
            int c = c0 + tc*4 + j;
            if (c < CO) {
                float v = acc[i][j] + bias[c];
                C[(size_t)r*CO + c] = v;
                if (mode == 3) c16[(size_t)r*128 + c] = __float2half_rn(v);
            }
        }
    }
}

// ---------- f16 HMMA GEMM: mode2 qkv epilogue, mode1 residual-relu ----------
#define G16_AS   0
#define G16_WS   34816
#define G16_SMEM 52224

__global__ __launch_bounds__(256, 2)
void gemm16_k(const __half* __restrict__ A, const __half* __restrict__ W,
              const float* __restrict__ bias, const float* __restrict__ R,
              float* __restrict__ C, int mode,
              __half* __restrict__ qh, __half* __restrict__ kh, __half* __restrict__ vt)
{
    extern __shared__ char smc[];
    const uint32_t sb = smem_u32(smc);
    const int tid  = threadIdx.x;
    const int lane = tid & 31;
    const int wid  = tid >> 5;
    const int r0   = blockIdx.x * 128;
    const int c0   = blockIdx.y * 64;

    {
        const uint4* Asrc = (const uint4*)A;
        #pragma unroll
        for (int i = 0; i < 8; i++) {
            int idx = tid + 256*i;
            int r = idx >> 4, c = idx & 15;
            *(uint4*)(smc + G16_AS + r*272 + c*16) = Asrc[(size_t)(r0 + r)*16 + c];
        }
        const uint4* Wsrc = (const uint4*)W;
        #pragma unroll
        for (int i = 0; i < 4; i++) {
            int idx = tid + 256*i;
            int r = idx >> 4, c = idx & 15;
            *(uint4*)(smc + G16_WS + r*272 + c*16) = Wsrc[(size_t)(c0 + r)*16 + c];
        }
    }
    __syncthreads();

    const int mrow = (wid >> 1) * 32;
    const int ncol = (wid & 1) * 32;
    const uint32_t aaddr = sb + G16_AS + (mrow + (lane & 15))*272 + ((lane >> 4) & 1)*16;
    const uint32_t baddr = sb + G16_WS + (ncol + (lane & 7) + ((lane >> 4) & 1)*8)*272
                           + ((lane >> 3) & 1)*16;

    float acc[2][4][4];
    #pragma unroll
    for (int mt = 0; mt < 2; mt++)
        #pragma unroll
        for (int nt = 0; nt < 4; nt++)
            #pragma unroll
            for (int e = 0; e < 4; e++) acc[mt][nt][e] = 0.f;

    #pragma unroll
    for (int k = 0; k < 8; k++) {
        uint32_t af[2][4], bf[2][4];
        ldsm4(af[0], aaddr + k*32);
        ldsm4(af[1], aaddr + 16*272 + k*32);
        ldsm4(bf[0], baddr + k*32);
        ldsm4(bf[1], baddr + 16*272 + k*32);
        #pragma unroll
        for (int mt = 0; mt < 2; mt++)
            #pragma unroll
            for (int p = 0; p < 2; p++) {
                mmaf16(acc[mt][2*p],   af[mt], bf[p]);
                mmaf16(acc[mt][2*p+1], af[mt], bf[p] + 2);
            }
    }

    const int rb = r0 + mrow + (lane >> 2);
    const int cb = c0 + ncol + 2*(lane & 3);
    #pragma unroll
    for (int mt = 0; mt < 2; mt++) {
        #pragma unroll
        for (int nt = 0; nt < 4; nt++) {
            int r = rb + mt*16;
            int c = cb + nt*8;
            float v0 = acc[mt][nt][0] + bias[c];
            float v1 = acc[mt][nt][1] + bias[c+1];
            float v2 = acc[mt][nt][2] + bias[c];
            float v3 = acc[mt][nt][3] + bias[c+1];
            if (mode == 2) {
                if (c < 128) {
                    *(__half2*)(qh + (size_t)r*128 + c)     = __floats2half2_rn(v0*RSQRT_HD, v1*RSQRT_HD);
                    *(__half2*)(qh + (size_t)(r+8)*128 + c) = __floats2half2_rn(v2*RSQRT_HD, v3*RSQRT_HD);
                } else if (c < 256) {
                    *(__half2*)(kh + (size_t)r*128 + (c-128))     = __floats2half2_rn(v0, v1);
                    *(__half2*)(kh + (size_t)(r+8)*128 + (c-128)) = __floats2half2_rn(v2, v3);
                } else {
                    vt[(size_t)(c-256)*NN + r]       = __float2half_rn(v0);
                    vt[(size_t)(c-255)*NN + r]       = __float2half_rn(v1);
                    vt[(size_t)(c-256)*NN + (r+8)]   = __float2half_rn(v2);
                    vt[(size_t)(c-255)*NN + (r+8)]   = __float2half_rn(v3);
                }
            } else {
                float2 R0 = *(const float2*)(R + (size_t)r*128 + c);
                float2 R1 = *(const float2*)(R + (size_t)(r+8)*128 + c);
                *(float2*)(C + (size_t)r*128 + c)     = make_float2(R0.x + fmaxf(v0,0.f), R0.y + fmaxf(v1,0.f));
                *(float2*)(C + (size_t)(r+8)*128 + c) = make_float2(R1.x + fmaxf(v2,0.f), R1.y + fmaxf(v3,0.f));
            }
        }
    }
}

// ---------- flash attention: 64q x 4 heads, 512 threads (16 warps, 4/SMSP) ----------
// warp w: head = w>>2, query-quarter qq = w&3 (one m16 tile, 64 keys/iter).
// Smem identical to R13: double-buffered Ks/Vs/Es stages + LUT.
#define STAGE     45056
#define LUT_OFF   90112
#define ATTN_SMEM 90240

__global__ __launch_bounds__(512, 1)
void attn_k(const __half* __restrict__ qh_g, const __half* __restrict__ kh_g,
            const __half* __restrict__ vt_g, const float* __restrict__ sp,
            const float* __restrict__ scale_ptr, __half* __restrict__ out)
{
    extern __shared__ char smc[];
    const uint32_t sb = smem_u32(smc);
    const int tid  = threadIdx.x;
    const int lane = tid & 31;
    const int wid  = tid >> 5;           // 0..15
    const int h    = wid >> 2;
    const int qq   = wid & 3;
    const int q0   = blockIdx.x * 64;
    const float scale = scale_ptr[0];
    const uint32_t lut = sb + LUT_OFF;

    if (tid <= 10) {
        float e = (tid == 0) ? expf(-scale) : expf(scale / (float)tid - scale);
        uint32_t hb = (uint32_t)__half_as_ushort(__float2half_rn(e));
        asm volatile("st.shared.u16 [%0], %1;" :: "r"(lut + tid*2), "r"(hb));
    }
    {   // stage Q: 64 rows x 16 uint4, 2/thread
        const uint4* qsrc = (const uint4*)(qh_g + (size_t)q0 * 128);
        #pragma unroll
        for (int i = 0; i < 2; i++) {
            int idx = tid + 512*i;
            int r = idx >> 4, c = idx & 15;
            *(uint4*)(smc + STAGE + r*272 + c*16) = qsrc[r*16 + c];
        }
    }
    __syncthreads();
    uint32_t qa[2][4];
    {
        uint32_t qaddr = sb + STAGE + (qq*16 + (lane & 15))*272 + (h*4 + (lane >> 4))*16;
        ldsm4(qa[0], qaddr);
        ldsm4(qa[1], qaddr + 32);
    }

    const uint32_t kaddr0 = sb + ((lane & 7) + ((lane >> 4) & 1)*8)*272
                            + h*64 + ((lane >> 3) & 1)*16;
    const uint32_t vaddr0 = sb + 17408 + (h*32 + (lane & 7) + ((lane >> 4) & 1)*8)*144
                            + ((lane >> 3) & 1)*16;
    const uint32_t baddr0 = sb + 35840 + (qq*16 + (lane >> 2))*144 + (lane & 3)*32;

    float O[4][4];
    #pragma unroll
    for (int i = 0; i < 4; i++)
        #pragma unroll
        for (int j = 0; j < 4; j++) O[i][j] = 0.f;
    float lacc[4] = {0.f, 0.f, 0.f, 0.f};
    const uint32_t ones2[2] = {0x3C003C00u, 0x3C003C00u};

    const uint4* ksrc = (const uint4*)kh_g;   // token row = 16 uint4
    const uint4* vsrc = (const uint4*)vt_g;   // d row = 1024 uint4

    const int kr = tid >> 4, kc = tid & 15;   // kr 0..31, 2 passes (+32)
    const int vr = tid >> 3, vc = tid & 7;    // vr 0..63, 2 passes (+64)
    const int bj  = kc >> 1;
    const int bc0 = (2*kc) & 3, bc1 = (2*kc + 1) & 3;

    uint4  krg[2], vrg[2];
    float4 brg[2];
    #pragma unroll
    for (int i = 0; i < 2; i++) {             // tile 0
        krg[i] = ksrc[(size_t)(kr + 32*i)*16 + kc];
        vrg[i] = vsrc[(size_t)(vr + 64*i)*1024 + vc];
        brg[i] = *(const float4*)(sp + (size_t)(q0 + kr + 32*i)*NN + kc*4);
    }
    {   // write stage0, preload tile1
        #pragma unroll
        for (int i = 0; i < 2; i++) {
            *(uint4*)(smc + (kr + 32*i)*272 + kc*16) = krg[i];
            *(uint4*)(smc + 17408 + (vr + 64*i)*144 + vc*16) = vrg[i];
            float4 s4 = brg[i];
            uint32_t p0 = (e16(s4.y, lut, scale) << 16) | e16(s4.x, lut, scale);
            uint32_t p1 = (e16(s4.w, lut, scale) << 16) | e16(s4.z, lut, scale);
            uint32_t bb = 35840 + (kr + 32*i)*144 + bj*4;
            *(uint32_t*)(smc + bb + bc0*32) = p0;
            *(uint32_t*)(smc + bb + bc1*32) = p1;
        }
        #pragma unroll
        for (int i = 0; i < 2; i++) {
            krg[i] = ksrc[(size_t)(64 + kr + 32*i)*16 + kc];
            vrg[i] = vsrc[(size_t)(vr + 64*i)*1024 + 8 + vc];
            brg[i] = *(const float4*)(sp + (size_t)(q0 + kr + 32*i)*NN + 64 + kc*4);
        }
    }

    for (int kb = 0; kb < NN/64; kb++) {
        __syncthreads();
        const uint32_t cur = (kb & 1) * STAGE;
        const uint32_t nxt = ((kb + 1) & 1) * STAGE;

        if (kb < NN/64 - 1) {
            #pragma unroll
            for (int i = 0; i < 2; i++) {
                *(uint4*)(smc + nxt + (kr + 32*i)*272 + kc*16) = krg[i];
                *(uint4*)(smc + nxt + 17408 + (vr + 64*i)*144 + vc*16) = vrg[i];
                float4 s4 = brg[i];
                uint32_t p0 = (e16(s4.y, lut, scale) << 16) | e16(s4.x, lut, scale);
                uint32_t p1 = (e16(s4.w, lut, scale) << 16) | e16(s4.z, lut, scale);
                uint32_t bb = nxt + 35840 + (kr + 32*i)*144 + bj*4;
                *(uint32_t*)(smc + bb + bc0*32) = p0;
                *(uint32_t*)(smc + bb + bc1*32) = p1;
            }
        }
        if (kb < NN/64 - 2) {
            const int k0n = (kb + 2) * 64;
            #pragma unroll
            for (int i = 0; i < 2; i++) {
                krg[i] = ksrc[(size_t)(k0n + kr + 32*i)*16 + kc];
                vrg[i] = vsrc[(size_t)(vr + 64*i)*1024 + (k0n >> 3) + vc];
                brg[i] = *(const float4*)(sp + (size_t)(q0 + kr + 32*i)*NN + k0n + kc*4);
            }
        }

        // ---- S = Q K^T (one m-tile, 8 n-tiles, 2 k-steps) ----
        float S[8][4];
        #pragma unroll
        for (int j = 0; j < 8; j++)
            #pragma unroll
            for (int t = 0; t < 4; t++) S[j][t] = 0.f;
        #pragma unroll
        for (int s = 0; s < 2; s++) {
            #pragma unroll
            for (int p = 0; p < 4; p++) {
                uint32_t kbf[4];
                ldsm4(kbf, kaddr0 + cur + p*(16*272) + s*32);
                mmaf16(S[2*p],   qa[s], kbf);
                mmaf16(S[2*p+1], qa[s], kbf + 2);
            }
        }

        // ---- softmax: p = ex2((S-4)*L2E) * E' ----
        uint32_t pk[4][4];
        {
            const uint32_t bmt = baddr0 + cur;
            uint32_t eL[4], eL2[4], eH[4], eH2[4];
            asm volatile("ld.shared.v4.b32 {%0,%1,%2,%3}, [%4];"
                : "=r"(eL[0]),"=r"(eL[1]),"=r"(eL[2]),"=r"(eL[3]) : "r"(bmt));
            asm volatile("ld.shared.v4.b32 {%0,%1,%2,%3}, [%4];"
                : "=r"(eL2[0]),"=r"(eL2[1]),"=r"(eL2[2]),"=r"(eL2[3]) : "r"(bmt + 16));
            asm volatile("ld.shared.v4.b32 {%0,%1,%2,%3}, [%4];"
                : "=r"(eH[0]),"=r"(eH[1]),"=r"(eH[2]),"=r"(eH[3]) : "r"(bmt + 8*144));
            asm volatile("ld.shared.v4.b32 {%0,%1,%2,%3}, [%4];"
                : "=r"(eH2[0]),"=r"(eH2[1]),"=r"(eH2[2]),"=r"(eH2[3]) : "r"(bmt + 8*144 + 16));
            #pragma unroll
            for (int j = 0; j < 8; j++) {
                uint32_t ePL = (j < 4) ? eL[j] : eL2[j-4];
                uint32_t ePH = (j < 4) ? eH[j] : eH2[j-4];
                uint32_t u0 = ex2h2(packh2(fmaf(S[j][1], L2E, MSH),
                                           fmaf(S[j][0], L2E, MSH)));
                uint32_t u1 = ex2h2(packh2(fmaf(S[j][3], L2E, MSH),
                                           fmaf(S[j][2], L2E, MSH)));
                int s = j >> 1, o = (j & 1) * 2;
                pk[s][o]     = mulh2(u0, ePL);
                pk[s][o + 1] = mulh2(u1, ePH);
            }
        }

        // ---- O += P V ; l += P·1 ----
        #pragma unroll
        for (int s = 0; s < 4; s++) {
            uint32_t vb[8];
            ldsm4(vb,     vaddr0 + cur + s*32);
            ldsm4(vb + 4, vaddr0 + cur + 16*144 + s*32);
            mmaf16(O[0], pk[s], vb);
            mmaf16(O[1], pk[s], vb + 2);
            mmaf16(O[2], pk[s], vb + 4);
            mmaf16(O[3], pk[s], vb + 6);
            mmaf16(lacc, pk[s], ones2);
        }
    }

    // finalize: lacc[0]=row-r sum, lacc[2]=row-(r+8) sum
    {
        const float i0 = 1.0f / lacc[0];
        const float i1 = 1.0f / lacc[2];
        const int r  = q0 + qq*16 + (lane >> 2);
        const int cb = h*32 + 2*(lane & 3);
        #pragma unroll
        for (int j = 0; j < 4; j++) {
            *(__half2*)(out + (size_t)r*128 + cb + 8*j)     = __floats2half2_rn(O[j][0]*i0, O[j][1]*i0);
            *(__half2*)(out + (size_t)(r+8)*128 + cb + 8*j) = __floats2half2_rn(O[j][2]*i1, O[j][3]*i1);
        }
    }
}

// ---------- log_softmax ----------
__global__ __launch_bounds__(256)
void logsoftmax_k(float* __restrict__ io)
{
    int row  = blockIdx.x * 8 + (threadIdx.x >> 5);
    int lane = threadIdx.x & 31;
    float* p = io + (size_t)row * OUTD;

    float a = p[lane];
    float b = (lane < 8) ? p[lane + 32] : -CUDART_INF_F;

    float mx = fmaxf(a, b);
    #pragma unroll
    for (int off = 16; off; off >>= 1)
        mx = fmaxf(mx, __shfl_xor_sync(0xffffffffu, mx, off));

    float e = __expf(a - mx) + ((lane < 8) ? __expf(b - mx) : 0.f);
    #pragma unroll
    for (int off = 16; off; off >>= 1)
        e += __shfl_xor_sync(0xffffffffu, e, off);

    float lse = mx + logf(e);
    p[lane] = a - lse;
    if (lane < 8) p[lane + 32] = b - lse;
}

// ---------- launch ----------
extern "C" void kernel_launch(void* const* d_in, const int* in_sizes, int n_in,
                              void* d_out, int out_size)
{
    (void)in_sizes; (void)n_in; (void)out_size;
    const float* x     = (const float*)d_in[0];
    const float* sp    = (const float*)d_in[2];
    const float* W_in  = (const float*)d_in[3];
    const float* b_in  = (const float*)d_in[4];
    const float* ipw   = (const float*)d_in[5];
    const float* ipb   = (const float*)d_in[6];
    const float* opw   = (const float*)d_in[7];
    const float* opb   = (const float*)d_in[8];
    const float* Wout  = (const float*)d_in[9];
    const float* bout  = (const float*)d_in[10];
    const float* scale = (const float*)d_in[11];
    float* out = (float*)d_out;

    float *gh, *gh2;
    __half *gh16, *gq, *gk, *gv, *gao, *gipw16, *gopw16;
    cudaGetSymbolAddress((void**)&gh,     g_h);
    cudaGetSymbolAddress((void**)&gh2,    g_h2);
    cudaGetSymbolAddress((void**)&gh16,   g_h16);
    cudaGetSymbolAddress((void**)&gq,     g_qh);
    cudaGetSymbolAddress((void**)&gk,     g_kh);
    cudaGetSymbolAddress((void**)&gv,     g_vt);
    cudaGetSymbolAddress((void**)&gao,    g_ao);
    cudaGetSymbolAddress((void**)&gipw16, g_ipw16);
    cudaGetSymbolAddress((void**)&gopw16, g_opw16);

    cudaFuncSetAttribute(gemm_k,   cudaFuncAttributeMaxDynamicSharedMemorySize, GEMM_SMEM_BYTES);
    cudaFuncSetAttribute(gemm16_k, cudaFuncAttributeMaxDynamicSharedMemorySize, G16_SMEM);
    cudaFuncSetAttribute(attn_k,   cudaFuncAttributeMaxDynamicSharedMemorySize, ATTN_SMEM);

    wcvt_k<<<64, 256>>>(ipw, opw, gipw16, gopw16);
    gemm_k<<<dim3(NN/64, 2), 256, GEMM_SMEM_BYTES>>>(x, W_in, b_in, gh, HID, 3, gh16);
    gemm16_k<<<dim3(NN/128, 6), 256, G16_SMEM>>>(gh16, gipw16, ipb, nullptr, nullptr, 2,
                                                 gq, gk, gv);
    attn_k<<<NN/64, 512, ATTN_SMEM>>>(gq, gk, gv, sp, scale, gao);
    gemm16_k<<<dim3(NN/128, 2), 256, G16_SMEM>>>(gao, gopw16, opb, gh, gh2, 1,
                                                 nullptr, nullptr, nullptr);
    gemm_k<<<dim3(NN/64, 1), 256, GEMM_SMEM_BYTES>>>(gh2, Wout, bout, out, OUTD, 0, nullptr);
    logsoftmax_k<<<NN/8, 256>>>(out);
}

// round 15
// speedup vs baseline: 1.1587x; 1.0456x over previous
#include <cuda_runtime.h>
#include <cuda_fp16.h>
#include <math_constants.h>
#include <cstdint>

#define NN    8192
#define HID   128
#define OUTD  40
#define RSQRT_HD 0.17677669529663687f
#define L2E      1.4426950408889634f
#define MSH      (-4.0f * 1.4426950408889634f)

__device__ __align__(16) float  g_h   [NN * HID];
__device__ __align__(16) __half g_h16 [NN * HID];
__device__ __align__(16) __half g_qh  [NN * HID];
__device__ __align__(16) __half g_kh  [NN * HID];
__device__ __align__(16) __half g_vt  [HID * NN];
__device__ __align__(16) __half g_ao  [NN * HID];
__device__ __align__(16) float  g_h2  [NN * HID];
__device__ __align__(16) __half g_ipw16[3*HID*HID];
__device__ __align__(16) __half g_opw16[HID*HID];

__device__ __forceinline__ uint32_t smem_u32(const void* p){
    uint32_t a;
    asm("{ .reg .u64 t; cvta.to.shared.u64 t, %1; cvt.u32.u64 %0, t; }" : "=r"(a) : "l"(p));
    return a;
}
__device__ __forceinline__ void ldsm4(uint32_t r[4], uint32_t addr){
    asm volatile("ldmatrix.sync.aligned.m8n8.x4.shared.b16 {%0,%1,%2,%3}, [%4];"
        : "=r"(r[0]), "=r"(r[1]), "=r"(r[2]), "=r"(r[3]) : "r"(addr));
}
__device__ __forceinline__ void mmaf16(float c[4], const uint32_t a[4], const uint32_t b[2]){
    asm volatile("mma.sync.aligned.m16n8k16.row.col.f32.f16.f16.f32 "
        "{%0,%1,%2,%3}, {%4,%5,%6,%7}, {%8,%9}, {%0,%1,%2,%3};"
        : "+f"(c[0]), "+f"(c[1]), "+f"(c[2]), "+f"(c[3])
        : "r"(a[0]), "r"(a[1]), "r"(a[2]), "r"(a[3]), "r"(b[0]), "r"(b[1]));
}
__device__ __forceinline__ uint32_t packh2(float hi, float lo){
    uint32_t r; asm("cvt.rn.f16x2.f32 %0, %1, %2;" : "=r"(r) : "f"(hi), "f"(lo)); return r;
}
__device__ __forceinline__ uint32_t ex2h2(uint32_t a){
    uint32_t d; asm("ex2.approx.f16x2 %0, %1;" : "=r"(d) : "r"(a)); return d;
}
__device__ __forceinline__ uint32_t mulh2(uint32_t a, uint32_t b){
    uint32_t d; asm("mul.rn.f16x2 %0, %1, %2;" : "=r"(d) : "r"(a), "r"(b)); return d;
}
__device__ __forceinline__ void cp16(uint32_t dst, const void* src){
    asm volatile("cp.async.cg.shared.global [%0], [%1], 16;" :: "r"(dst), "l"(src) : "memory");
}
#define CP_COMMIT() asm volatile("cp.async.commit_group;" ::: "memory")
#define CP_WAIT0()  asm volatile("cp.async.wait_group 0;" ::: "memory")

__device__ __forceinline__ uint32_t e16(float s, uint32_t lutaddr, float scale){
    int idx = __float2int_rn(s);
    uint32_t h;
    if (__int2float_rn(idx) == s && idx >= 0 && idx <= 10) {
        asm volatile("ld.shared.u16 %0, [%1];" : "=r"(h) : "r"(lutaddr + idx*2));
    } else {
        float ss = (isnan(s) || isinf(s)) ? -1.0f : s;
        float r = __fdividef(1.0f, ss);
        if (isnan(r) || isinf(r)) r = 0.0f;
        float e = exp2f(fmaf(scale, r, -scale) * L2E);
        h = (uint32_t)__half_as_ushort(__float2half_rn(e));
    }
    return h;
}

// ---------- weight convert ----------
__global__ __launch_bounds__(256)
void wcvt_k(const float* __restrict__ a, const float* __restrict__ b,
            __half* __restrict__ a16, __half* __restrict__ b16)
{
    int idx = blockIdx.x*256 + threadIdx.x;
    for (int i = idx; i < 3*HID*HID; i += 16384) a16[i] = __float2half_rn(a[i]);
    for (int i = idx; i < HID*HID;   i += 16384) b16[i] = __float2half_rn(b[i]);
}

// ---------- fp32 GEMM (gemm1 mode3: fp32 + f16 copy; Wout mode0) ----------
#define GEMM_SMEM_BYTES ((2*128*64 + 64*132) * 4)

__global__ __launch_bounds__(256, 2)
void gemm_k(const float* __restrict__ A, const float* __restrict__ W,
            const float* __restrict__ bias, float* __restrict__ C,
            int CO, int mode, __half* __restrict__ c16)
{
    extern __shared__ float sm[];
    float* At  = sm;
    float* Wt  = sm + 128*64;
    float* Stg = sm + 2*128*64;
    const int r0  = blockIdx.x * 64;
    const int c0  = blockIdx.y * 64;
    const int tid = threadIdx.x;

    {
        const float4* Af4 = (const float4*)(A + (size_t)r0 * 128);
        float4* Sf4 = (float4*)Stg;
        #pragma unroll
        for (int i = 0; i < 8; i++) {
            int idx = tid + 256*i;
            int r = idx >> 5, d4 = idx & 31;
            Sf4[r*33 + d4] = Af4[r*32 + d4];
        }
    }
    __syncthreads();
    {
        #pragma unroll
        for (int i = 0; i < 8; i++) {
            int idx = tid + 256*i;
            int r = idx & 63, d4 = idx >> 6;
            float4 v = *(const float4*)&Stg[r*132 + d4*4];
            At[(4*d4+0)*64 + r] = v.x; At[(4*d4+1)*64 + r] = v.y;
            At[(4*d4+2)*64 + r] = v.z; At[(4*d4+3)*64 + r] = v.w;
        }
    }
    __syncthreads();
    {
        const float4* Wf4 = (const float4*)W;
        float4* Sf4 = (float4*)Stg;
        #pragma unroll
        for (int i = 0; i < 8; i++) {
            int idx = tid + 256*i;
            int c = idx >> 5, d4 = idx & 31;
            float4 v = make_float4(0.f,0.f,0.f,0.f);
            if (c0 + c < CO) v = Wf4[(size_t)(c0 + c)*32 + d4];
            Sf4[c*33 + d4] = v;
        }
    }
    __syncthreads();
    {
        #pragma unroll
        for (int i = 0; i < 8; i++) {
            int idx = tid + 256*i;
            int c = idx & 63, d4 = idx >> 6;
            float4 v = *(const float4*)&Stg[c*132 + d4*4];
            Wt[(4*d4+0)*64 + c] = v.x; Wt[(4*d4+1)*64 + c] = v.y;
            Wt[(4*d4+2)*64 + c] = v.z; Wt[(4*d4+3)*64 + c] = v.w;
        }
    }
    __syncthreads();

    const int tr = tid >> 4;
    const int tc = tid & 15;
    float acc[4][4];
    #pragma unroll
    for (int i = 0; i < 4; i++)
        #pragma unroll
        for (int j = 0; j < 4; j++) acc[i][j] = 0.f;

    #pragma unroll 8
    for (int d = 0; d < 128; d++) {
        float4 a = *(const float4*)&At[d*64 + tr*4];
        float4 w = *(const float4*)&Wt[d*64 + tc*4];
        float av[4] = {a.x, a.y, a.z, a.w};
        float wv[4] = {w.x, w.y, w.z, w.w};
        #pragma unroll
        for (int i = 0; i < 4; i++)
            #pragma unroll
            for (int j = 0; j < 4; j++)
                acc[i][j] = fmaf(av[i], wv[j], acc[i][j]);
    }

    #pragma unroll
    for (int i = 0; i < 4; i++) {
        int r = r0 + tr*4 + i;
        #pragma unroll
        for (int j = 0; j < 4; j++) {
            int c = c0 + tc*4 + j;
            if (c < CO) {
                float v = acc[i][j] + bias[c];
                C[(size_t)r*CO + c] = v;
                if (mode == 3) c16[(size_t)r*128 + c] = __float2half_rn(v);
            }
        }
    }
}

// ---------- f16 HMMA GEMM: mode2 qkv epilogue, mode1 residual-relu ----------
#define G16_AS   0
#define G16_WS   34816
#define G16_SMEM 52224

__global__ __launch_bounds__(256, 2)
void gemm16_k(const __half* __restrict__ A, const __half* __restrict__ W,
              const float* __restrict__ bias, const float* __restrict__ R,
              float* __restrict__ C, int mode,
              __half* __restrict__ qh, __half* __restrict__ kh, __half* __restrict__ vt)
{
    extern __shared__ char smc[];
    const uint32_t sb = smem_u32(smc);
    const int tid  = threadIdx.x;
    const int lane = tid & 31;
    const int wid  = tid >> 5;
    const int r0   = blockIdx.x * 128;
    const int c0   = blockIdx.y * 64;

    {
        const uint4* Asrc = (const uint4*)A;
        #pragma unroll
        for (int i = 0; i < 8; i++) {
            int idx = tid + 256*i;
            int r = idx >> 4, c = idx & 15;
            *(uint4*)(smc + G16_AS + r*272 + c*16) = Asrc[(size_t)(r0 + r)*16 + c];
        }
        const uint4* Wsrc = (const uint4*)W;
        #pragma unroll
        for (int i = 0; i < 4; i++) {
            int idx = tid + 256*i;
            int r = idx >> 4, c = idx & 15;
            *(uint4*)(smc + G16_WS + r*272 + c*16) = Wsrc[(size_t)(c0 + r)*16 + c];
        }
    }
    __syncthreads();

    const int mrow = (wid >> 1) * 32;
    const int ncol = (wid & 1) * 32;
    const uint32_t aaddr = sb + G16_AS + (mrow + (lane & 15))*272 + ((lane >> 4) & 1)*16;
    const uint32_t baddr = sb + G16_WS + (ncol + (lane & 7) + ((lane >> 4) & 1)*8)*272
                           + ((lane >> 3) & 1)*16;

    float acc[2][4][4];
    #pragma unroll
    for (int mt = 0; mt < 2; mt++)
        #pragma unroll
        for (int nt = 0; nt < 4; nt++)
            #pragma unroll
            for (int e = 0; e < 4; e++) acc[mt][nt][e] = 0.f;

    #pragma unroll
    for (int k = 0; k < 8; k++) {
        uint32_t af[2][4], bf[2][4];
        ldsm4(af[0], aaddr + k*32);
        ldsm4(af[1], aaddr + 16*272 + k*32);
        ldsm4(bf[0], baddr + k*32);
        ldsm4(bf[1], baddr + 16*272 + k*32);
        #pragma unroll
        for (int mt = 0; mt < 2; mt++)
            #pragma unroll
            for (int p = 0; p < 2; p++) {
                mmaf16(acc[mt][2*p],   af[mt], bf[p]);
                mmaf16(acc[mt][2*p+1], af[mt], bf[p] + 2);
            }
    }

    const int rb = r0 + mrow + (lane >> 2);
    const int cb = c0 + ncol + 2*(lane & 3);
    #pragma unroll
    for (int mt = 0; mt < 2; mt++) {
        #pragma unroll
        for (int nt = 0; nt < 4; nt++) {
            int r = rb + mt*16;
            int c = cb + nt*8;
            float v0 = acc[mt][nt][0] + bias[c];
            float v1 = acc[mt][nt][1] + bias[c+1];
            float v2 = acc[mt][nt][2] + bias[c];
            float v3 = acc[mt][nt][3] + bias[c+1];
            if (mode == 2) {
                if (c < 128) {
                    *(__half2*)(qh + (size_t)r*128 + c)     = __floats2half2_rn(v0*RSQRT_HD, v1*RSQRT_HD);
                    *(__half2*)(qh + (size_t)(r+8)*128 + c) = __floats2half2_rn(v2*RSQRT_HD, v3*RSQRT_HD);
                } else if (c < 256) {
                    *(__half2*)(kh + (size_t)r*128 + (c-128))     = __floats2half2_rn(v0, v1);
                    *(__half2*)(kh + (size_t)(r+8)*128 + (c-128)) = __floats2half2_rn(v2, v3);
                } else {
                    vt[(size_t)(c-256)*NN + r]       = __float2half_rn(v0);
                    vt[(size_t)(c-255)*NN + r]       = __float2half_rn(v1);
                    vt[(size_t)(c-256)*NN + (r+8)]   = __float2half_rn(v2);
                    vt[(size_t)(c-255)*NN + (r+8)]   = __float2half_rn(v3);
                }
            } else {
                float2 R0 = *(const float2*)(R + (size_t)r*128 + c);
                float2 R1 = *(const float2*)(R + (size_t)(r+8)*128 + c);
                *(float2*)(C + (size_t)r*128 + c)     = make_float2(R0.x + fmaxf(v0,0.f), R0.y + fmaxf(v1,0.f));
                *(float2*)(C + (size_t)(r+8)*128 + c) = make_float2(R1.x + fmaxf(v2,0.f), R1.y + fmaxf(v3,0.f));
            }
        }
    }
}

// ---------- flash attention: 64q x 4h, 16 warps = (head, q-half, k-half) ----------
// Warp covers 32q x 32k of one head (2 m-tiles). K/V via cp.async double buffer.
// End: kh=1 partial O/l combined into kh=0 via smem (fp32 exact, one time).
#define STAGE     45056
#define LUT_OFF   90112
#define ATTN_SMEM 90240

__global__ __launch_bounds__(512, 1)
void attn_k(const __half* __restrict__ qh_g, const __half* __restrict__ kh_g,
            const __half* __restrict__ vt_g, const float* __restrict__ sp,
            const float* __restrict__ scale_ptr, __half* __restrict__ out)
{
    extern __shared__ char smc[];
    const uint32_t sb = smem_u32(smc);
    const int tid  = threadIdx.x;
    const int lane = tid & 31;
    const int wid  = tid >> 5;           // 0..15
    const int h    = wid >> 2;
    const int qhf  = (wid >> 1) & 1;     // query half
    const int khf  = wid & 1;            // key half
    const int q0   = blockIdx.x * 64;
    const float scale = scale_ptr[0];
    const uint32_t lut = sb + LUT_OFF;

    if (tid <= 10) {
        float e = (tid == 0) ? expf(-scale) : expf(scale / (float)tid - scale);
        uint32_t hb = (uint32_t)__half_as_ushort(__float2half_rn(e));
        asm volatile("st.shared.u16 [%0], %1;" :: "r"(lut + tid*2), "r"(hb));
    }
    {   // stage Q in stage1 Ks region
        const uint4* qsrc = (const uint4*)(qh_g + (size_t)q0 * 128);
        #pragma unroll
        for (int i = 0; i < 2; i++) {
            int idx = tid + 512*i;
            int r = idx >> 4, c = idx & 15;
            *(uint4*)(smc + STAGE + r*272 + c*16) = qsrc[r*16 + c];
        }
    }
    __syncthreads();
    uint32_t qa[2][2][4];
    #pragma unroll
    for (int mt = 0; mt < 2; mt++) {
        uint32_t qaddr = sb + STAGE + (qhf*32 + mt*16 + (lane & 15))*272
                         + (h*4 + (lane >> 4))*16;
        ldsm4(qa[mt][0], qaddr);
        ldsm4(qa[mt][1], qaddr + 32);
    }

    // per-lane addresses (khf selects key half)
    const uint32_t kaddr0 = sb + (khf*32 + (lane & 7) + ((lane >> 4) & 1)*8)*272
                            + h*64 + ((lane >> 3) & 1)*16;
    const uint32_t vaddr0 = sb + 17408 + (h*32 + (lane & 7) + ((lane >> 4) & 1)*8)*144
                            + khf*64 + ((lane >> 3) & 1)*16;
    const uint32_t baddr0 = sb + 35840 + (qhf*32 + (lane >> 2))*144 + (lane & 3)*32 + khf*16;

    float O[2][4][4];
    #pragma unroll
    for (int mt = 0; mt < 2; mt++)
        #pragma unroll
        for (int i = 0; i < 4; i++)
            #pragma unroll
            for (int j = 0; j < 4; j++) O[mt][i][j] = 0.f;
    float lacc[2][4];
    #pragma unroll
    for (int mt = 0; mt < 2; mt++)
        #pragma unroll
        for (int e = 0; e < 4; e++) lacc[mt][e] = 0.f;
    const uint32_t ones2[2] = {0x3C003C00u, 0x3C003C00u};

    const uint4* ksrc = (const uint4*)kh_g;   // token row = 16 uint4
    const uint4* vsrc = (const uint4*)vt_g;   // d row = 1024 uint4

    const int kr = tid >> 4, kc = tid & 15;   // K/E producer pattern
    const int vr = tid >> 3, vc = tid & 7;    // V producer pattern
    const int bj  = kc >> 1;
    const int bc0 = (2*kc) & 3, bc1 = (2*kc + 1) & 3;

    float4 brg[2];
    {   // tile 0: cp.async K/V -> stage0; E from registers
        #pragma unroll
        for (int i = 0; i < 2; i++) {
            cp16(sb + (kr + 32*i)*272 + kc*16, ksrc + (size_t)(kr + 32*i)*16 + kc);
            cp16(sb + 17408 + (vr + 64*i)*144 + vc*16, vsrc + (size_t)(vr + 64*i)*1024 + vc);
        }
        CP_COMMIT();
        #pragma unroll
        for (int i = 0; i < 2; i++)
            brg[i] = *(const float4*)(sp + (size_t)(q0 + kr + 32*i)*NN + kc*4);
        #pragma unroll
        for (int i = 0; i < 2; i++) {
            float4 s4 = brg[i];
            uint32_t p0 = (e16(s4.y, lut, scale) << 16) | e16(s4.x, lut, scale);
            uint32_t p1 = (e16(s4.w, lut, scale) << 16) | e16(s4.z, lut, scale);
            uint32_t bb = 35840 + (kr + 32*i)*144 + bj*4;
            *(uint32_t*)(smc + bb + bc0*32) = p0;
            *(uint32_t*)(smc + bb + bc1*32) = p1;
        }
        #pragma unroll
        for (int i = 0; i < 2; i++)
            brg[i] = *(const float4*)(sp + (size_t)(q0 + kr + 32*i)*NN + 64 + kc*4);
    }

    for (int kb = 0; kb < NN/64; kb++) {
        CP_WAIT0();
        __syncthreads();
        const uint32_t cur = (kb & 1) * STAGE;
        const uint32_t nxt = ((kb + 1) & 1) * STAGE;

        if (kb < NN/64 - 1) {       // tile kb+1 -> nxt
            const int k0n = (kb + 1) * 64;
            #pragma unroll
            for (int i = 0; i < 2; i++) {
                cp16(sb + nxt + (kr + 32*i)*272 + kc*16,
                     ksrc + (size_t)(k0n + kr + 32*i)*16 + kc);
                cp16(sb + nxt + 17408 + (vr + 64*i)*144 + vc*16,
                     vsrc + (size_t)(vr + 64*i)*1024 + (k0n >> 3) + vc);
            }
            CP_COMMIT();
            #pragma unroll
            for (int i = 0; i < 2; i++) {
                float4 s4 = brg[i];
                uint32_t p0 = (e16(s4.y, lut, scale) << 16) | e16(s4.x, lut, scale);
                uint32_t p1 = (e16(s4.w, lut, scale) << 16) | e16(s4.z, lut, scale);
                uint32_t bb = nxt + 35840 + (kr + 32*i)*144 + bj*4;
                *(uint32_t*)(smc + bb + bc0*32) = p0;
                *(uint32_t*)(smc + bb + bc1*32) = p1;
            }
        }
        if (kb < NN/64 - 2) {
            const int k0n = (kb + 2) * 64;
            #pragma unroll
            for (int i = 0; i < 2; i++)
                brg[i] = *(const float4*)(sp + (size_t)(q0 + kr + 32*i)*NN + k0n + kc*4);
        }

        // ---- S = Q K^T : 2 m-tiles x 4 n-tiles (32 keys) x 2 k-steps ----
        float S[2][4][4];
        #pragma unroll
        for (int mt = 0; mt < 2; mt++)
            #pragma unroll
            for (int j = 0; j < 4; j++)
                #pragma unroll
                for (int t = 0; t < 4; t++) S[mt][j][t] = 0.f;
        #pragma unroll
        for (int s = 0; s < 2; s++) {
            #pragma unroll
            for (int p = 0; p < 2; p++) {
                uint32_t kbf[4];
                ldsm4(kbf, kaddr0 + cur + p*(16*272) + s*32);
                #pragma unroll
                for (int mt = 0; mt < 2; mt++) {
                    mmaf16(S[mt][2*p],   qa[mt][s], kbf);
                    mmaf16(S[mt][2*p+1], qa[mt][s], kbf + 2);
                }
            }
        }

        // ---- softmax: p = ex2((S-4)*L2E) * E' ----
        uint32_t pk[2][2][4];
        #pragma unroll
        for (int mt = 0; mt < 2; mt++) {
            const uint32_t bmt = baddr0 + cur + mt*(16*144);
            uint32_t eL[4], eH[4];
            asm volatile("ld.shared.v4.b32 {%0,%1,%2,%3}, [%4];"
                : "=r"(eL[0]),"=r"(eL[1]),"=r"(eL[2]),"=r"(eL[3]) : "r"(bmt));
            asm volatile("ld.shared.v4.b32 {%0,%1,%2,%3}, [%4];"
                : "=r"(eH[0]),"=r"(eH[1]),"=r"(eH[2]),"=r"(eH[3]) : "r"(bmt + 8*144));
            #pragma unroll
            for (int j = 0; j < 4; j++) {
                uint32_t u0 = ex2h2(packh2(fmaf(S[mt][j][1], L2E, MSH),
                                           fmaf(S[mt][j][0], L2E, MSH)));
                uint32_t u1 = ex2h2(packh2(fmaf(S[mt][j][3], L2E, MSH),
                                           fmaf(S[mt][j][2], L2E, MSH)));
                int s = j >> 1, o = (j & 1) * 2;
                pk[mt][s][o]     = mulh2(u0, eL[j]);
                pk[mt][s][o + 1] = mulh2(u1, eH[j]);
            }
        }

        // ---- O += P V ; l += P·1 ----
        #pragma unroll
        for (int s = 0; s < 2; s++) {
            uint32_t vb[8];
            ldsm4(vb,     vaddr0 + cur + s*32);
            ldsm4(vb + 4, vaddr0 + cur + 16*144 + s*32);
            #pragma unroll
            for (int mt = 0; mt < 2; mt++) {
                mmaf16(O[mt][0], pk[mt][s], vb);
                mmaf16(O[mt][1], pk[mt][s], vb + 2);
                mmaf16(O[mt][2], pk[mt][s], vb + 4);
                mmaf16(O[mt][3], pk[mt][s], vb + 6);
                mmaf16(lacc[mt], pk[mt][s], ones2);
            }
        }
    }

    // ---- cross-k-half combine (fp32 exact) ----
    __syncthreads();
    float* red = (float*)smc;                 // reuse stage0: 8 pairs x 36 regs x 32 lanes
    const int wpair = h*2 + qhf;              // 0..7
    if (khf == 1) {
        #pragma unroll
        for (int mt = 0; mt < 2; mt++)
            #pragma unroll
            for (int dt = 0; dt < 4; dt++)
                #pragma unroll
                for (int e = 0; e < 4; e++)
                    red[(wpair*36 + mt*16 + dt*4 + e)*32 + lane] = O[mt][dt][e];
        #pragma unroll
        for (int mt = 0; mt < 2; mt++) {
            red[(wpair*36 + 32 + mt*2 + 0)*32 + lane] = lacc[mt][0];
            red[(wpair*36 + 32 + mt*2 + 1)*32 + lane] = lacc[mt][2];
        }
    }
    __syncthreads();
    if (khf == 0) {
        #pragma unroll
        for (int mt = 0; mt < 2; mt++) {
            #pragma unroll
            for (int dt = 0; dt < 4; dt++)
                #pragma unroll
                for (int e = 0; e < 4; e++)
                    O[mt][dt][e] += red[(wpair*36 + mt*16 + dt*4 + e)*32 + lane];
            const float l0 = lacc[mt][0] + red[(wpair*36 + 32 + mt*2 + 0)*32 + lane];
            const float l1 = lacc[mt][2] + red[(wpair*36 + 32 + mt*2 + 1)*32 + lane];
            const float i0 = 1.0f / l0;
            const float i1 = 1.0f / l1;
            const int r  = q0 + qhf*32 + mt*16 + (lane >> 2);
            const int cb = h*32 + 2*(lane & 3);
            #pragma unroll
            for (int dt = 0; dt < 4; dt++) {
                *(__half2*)(out + (size_t)r*128 + cb + 8*dt)     = __floats2half2_rn(O[mt][dt][0]*i0, O[mt][dt][1]*i0);
                *(__half2*)(out + (size_t)(r+8)*128 + cb + 8*dt) = __floats2half2_rn(O[mt][dt][2]*i1, O[mt][dt][3]*i1);
            }
        }
    }
}

// ---------- log_softmax ----------
__global__ __launch_bounds__(256)
void logsoftmax_k(float* __restrict__ io)
{
    int row  = blockIdx.x * 8 + (threadIdx.x >> 5);
    int lane = threadIdx.x & 31;
    float* p = io + (size_t)row * OUTD;

    float a = p[lane];
    float b = (lane < 8) ? p[lane + 32] : -CUDART_INF_F;

    float mx = fmaxf(a, b);
    #pragma unroll
    for (int off = 16; off; off >>= 1)
        mx = fmaxf(mx, __shfl_xor_sync(0xffffffffu, mx, off));

    float e = __expf(a - mx) + ((lane < 8) ? __expf(b - mx) : 0.f);
    #pragma unroll
    for (int off = 16; off; off >>= 1)
        e += __shfl_xor_sync(0xffffffffu, e, off);

    float lse = mx + logf(e);
    p[lane] = a - lse;
    if (lane < 8) p[lane + 32] = b - lse;
}

// ---------- launch ----------
extern "C" void kernel_launch(void* const* d_in, const int* in_sizes, int n_in,
                              void* d_out, int out_size)
{
    (void)in_sizes; (void)n_in; (void)out_size;
    const float* x     = (const float*)d_in[0];
    const float* sp    = (const float*)d_in[2];
    const float* W_in  = (const float*)d_in[3];
    const float* b_in  = (const float*)d_in[4];
    const float* ipw   = (const float*)d_in[5];
    const float* ipb   = (const float*)d_in[6];
    const float* opw   = (const float*)d_in[7];
    const float* opb   = (const float*)d_in[8];
    const float* Wout  = (const float*)d_in[9];
    const float* bout  = (const float*)d_in[10];
    const float* scale = (const float*)d_in[11];
    float* out = (float*)d_out;

    float *gh, *gh2;
    __half *gh16, *gq, *gk, *gv, *gao, *gipw16, *gopw16;
    cudaGetSymbolAddress((void**)&gh,     g_h);
    cudaGetSymbolAddress((void**)&gh2,    g_h2);
    cudaGetSymbolAddress((void**)&gh16,   g_h16);
    cudaGetSymbolAddress((void**)&gq,     g_qh);
    cudaGetSymbolAddress((void**)&gk,     g_kh);
    cudaGetSymbolAddress((void**)&gv,     g_vt);
    cudaGetSymbolAddress((void**)&gao,    g_ao);
    cudaGetSymbolAddress((void**)&gipw16, g_ipw16);
    cudaGetSymbolAddress((void**)&gopw16, g_opw16);

    cudaFuncSetAttribute(gemm_k,   cudaFuncAttributeMaxDynamicSharedMemorySize, GEMM_SMEM_BYTES);
    cudaFuncSetAttribute(gemm16_k, cudaFuncAttributeMaxDynamicSharedMemorySize, G16_SMEM);
    cudaFuncSetAttribute(attn_k,   cudaFuncAttributeMaxDynamicSharedMemorySize, ATTN_SMEM);

    wcvt_k<<<64, 256>>>(ipw, opw, gipw16, gopw16);
    gemm_k<<<dim3(NN/64, 2), 256, GEMM_SMEM_BYTES>>>(x, W_in, b_in, gh, HID, 3, gh16);
    gemm16_k<<<dim3(NN/128, 6), 256, G16_SMEM>>>(gh16, gipw16, ipb, nullptr, nullptr, 2,
                                                 gq, gk, gv);
    attn_k<<<NN/64, 512, ATTN_SMEM>>>(gq, gk, gv, sp, scale, gao);
    gemm16_k<<<dim3(NN/128, 2), 256, G16_SMEM>>>(gao, gopw16, opb, gh, gh2, 1,
                                                 nullptr, nullptr, nullptr);
    gemm_k<<<dim3(NN/64, 1), 256, GEMM_SMEM_BYTES>>>(gh2, Wout, bout, out, OUTD, 0, nullptr);
    logsoftmax_k<<<NN/8, 256>>>(out);
}